// round 5
// baseline (speedup 1.0000x reference)
#include <cuda_runtime.h>
#include <cstdint>

// Problem dims (fixed)
#define L_DIM   1024
#define H_DIM   256
#define KWIN    16
#define R_TOTAL 16384
#define G3      768
#define KDIM    256

// Tiling
#define TILE_M  128
#define NTOT    192                 // 3 gates x 64 cols
#define BK      32
#define NCHUNK  (KDIM / BK)         // 8
#define THREADS 512

// Smem (floats), padded stride 36 -> conflict-free fragment loads
#define AS      36
#define BS      36
#define ABUF    (TILE_M * AS)       // 4608
#define BBUF    (NTOT * BS)         // 6912
#define BUFF    (ABUF + BBUF)       // 11520
#define NBUF    3
#define SMEM_BYTES (NBUF * BUFF * 4)   // 138240

// Scratch (allocation-free rule: device globals)
__device__ float g_G[R_TOTAL * G3];          // input projections incl. b_ih
__device__ float g_H[2][R_TOTAL * H_DIM];    // exact hidden state (ping-pong)
__device__ float g_Ht[2][R_TOTAL * H_DIM];   // tf32-rounded hidden state (GEMM A operand)
__device__ float g_Xr[R_TOTAL * KDIM];       // rna-rounded x
__device__ float g_Wir[G3 * KDIM];           // rna-rounded W_ih
__device__ float g_Whr[G3 * KDIM];           // rna-rounded W_hh

// ---------------------------------------------------------------------------
// helpers
// ---------------------------------------------------------------------------
__device__ __forceinline__ uint32_t smem_u32(const void* p) {
    uint32_t a;
    asm("{ .reg .u64 t; cvta.to.shared.u64 t, %1; cvt.u32.u64 %0, t; }" : "=r"(a) : "l"(p));
    return a;
}
__device__ __forceinline__ float tanh_apx(float x) {
    float y; asm("tanh.approx.f32 %0, %1;" : "=f"(y) : "f"(x)); return y;
}
__device__ __forceinline__ float sigm(float x) {
    return fmaf(tanh_apx(0.5f * x), 0.5f, 0.5f);
}
__device__ __forceinline__ float rna_tf32(float x) {
    float y; asm("cvt.rna.tf32.f32 %0, %1;" : "=f"(y) : "f"(x)); return y;
}

#define CP_ASYNC16(dst, src) \
    asm volatile("cp.async.cg.shared.global [%0], [%1], 16;" :: "r"(dst), "l"(src) : "memory")
#define CP_COMMIT() asm volatile("cp.async.commit_group;" ::: "memory")
#define CP_WAIT(n)  asm volatile("cp.async.wait_group %0;" :: "n"(n) : "memory")

#define CLUSTER_SYNC() do { \
    asm volatile("barrier.cluster.arrive.aligned;" ::: "memory"); \
    asm volatile("barrier.cluster.wait.aligned;" ::: "memory"); } while (0)

__device__ __forceinline__ void mma_tf32(float* d, const uint32_t* a, uint32_t b0, uint32_t b1) {
    asm volatile(
        "mma.sync.aligned.m16n8k8.row.col.f32.tf32.tf32.f32 "
        "{%0,%1,%2,%3}, {%4,%5,%6,%7}, {%8,%9}, {%0,%1,%2,%3};"
        : "+f"(d[0]), "+f"(d[1]), "+f"(d[2]), "+f"(d[3])
        : "r"(a[0]), "r"(a[1]), "r"(a[2]), "r"(a[3]), "r"(b0), "r"(b1));
}

// ---------------------------------------------------------------------------
// Shared GEMM mainloop: acc[3][2][2][4] += A[gm:gm+128, :256] x W[3x(n0:n0+64), :256]^T
// Triple-buffered cp.async ring, one barrier per chunk.
// ---------------------------------------------------------------------------
__device__ __forceinline__ void gemm_core(
    const float* __restrict__ A, const float* __restrict__ W,
    float* __restrict__ smf, uint32_t sb,
    int gm, int n0, int tid, int lane, int warp_m, int wn,
    float acc[3][2][2][4])
{
#pragma unroll
    for (int g = 0; g < 3; g++)
#pragma unroll
        for (int mt = 0; mt < 2; mt++)
#pragma unroll
            for (int nt = 0; nt < 2; nt++)
#pragma unroll
                for (int e = 0; e < 4; e++) acc[g][mt][nt][e] = 0.0f;

    auto issue = [&](int k0, int buf) {
        const uint32_t abase = sb + buf * (BUFF * 4);
#pragma unroll
        for (int i = 0; i < 2; i++) {                 // A: 1024 x 16B
            int j = tid + i * THREADS;
            int row = j >> 3, kv = (j & 7) << 2;
            CP_ASYNC16(abase + (row * AS + kv) * 4,
                       &A[(size_t)(gm + row) * KDIM + k0 + kv]);
        }
        const uint32_t bbase = abase + ABUF * 4;
#pragma unroll
        for (int i = 0; i < 3; i++) {                 // B: 1536 x 16B
            int j = tid + i * THREADS;
            int row = j >> 3, kv = (j & 7) << 2;      // row = g*64 + nloc
            int g = row >> 6, nl = row & 63;
            CP_ASYNC16(bbase + (row * BS + kv) * 4,
                       &W[(size_t)(g * H_DIM + n0 + nl) * KDIM + k0 + kv]);
        }
        CP_COMMIT();
    };

    issue(0, 0);
    issue(BK, 1);
#pragma unroll 1
    for (int c = 0; c < NCHUNK; c++) {
        if (c == NCHUNK - 1) { CP_WAIT(0); } else { CP_WAIT(1); }
        __syncthreads();
        if (c + 2 < NCHUNK) issue((c + 2) * BK, (c + 2) % 3);

        const uint32_t* Ab = (const uint32_t*)(smf + (c % 3) * BUFF);
        const uint32_t* Bb = Ab + ABUF;
#pragma unroll
        for (int ks = 0; ks < 4; ks++) {
            const int kk = ks * 8 + (lane & 3);
            uint32_t a[2][4];
#pragma unroll
            for (int mt = 0; mt < 2; mt++) {
                int r0 = warp_m * 32 + mt * 16 + (lane >> 2);
                a[mt][0] = Ab[(r0)     * AS + kk];
                a[mt][1] = Ab[(r0 + 8) * AS + kk];
                a[mt][2] = Ab[(r0)     * AS + kk + 4];
                a[mt][3] = Ab[(r0 + 8) * AS + kk + 4];
            }
#pragma unroll
            for (int g = 0; g < 3; g++) {
#pragma unroll
                for (int nt = 0; nt < 2; nt++) {
                    int nr = g * 64 + wn * 16 + nt * 8 + (lane >> 2);
                    uint32_t b0 = Bb[nr * BS + kk];
                    uint32_t b1 = Bb[nr * BS + kk + 4];
                    mma_tf32(acc[g][0][nt], a[0], b0, b1);
                    mma_tf32(acc[g][1][nt], a[1], b0, b1);
                }
            }
        }
    }
}

// ---------------------------------------------------------------------------
// prep: rna-round x, W_ih, W_hh into device scratch
// ---------------------------------------------------------------------------
__global__ __launch_bounds__(256) void prep_kernel(
    const float* __restrict__ x,
    const float* __restrict__ Wih,
    const float* __restrict__ Whh)
{
    int i = blockIdx.x * 256 + threadIdx.x;
    if (i < R_TOTAL * KDIM) g_Xr[i] = rna_tf32(x[i]);
    if (i < G3 * KDIM) {
        g_Wir[i] = rna_tf32(Wih[i]);
        g_Whr[i] = rna_tf32(Whh[i]);
    }
}

// ---------------------------------------------------------------------------
// proj: G = x @ W_ih^T + b_ih
// ---------------------------------------------------------------------------
__global__ __launch_bounds__(THREADS, 1) void proj_kernel(const float* __restrict__ bih)
{
    extern __shared__ float smf[];
    const uint32_t sb = smem_u32(smf);
    const int tid = threadIdx.x;
    const int lane = tid & 31, wid = tid >> 5;
    const int warp_m = wid & 3, wn = wid >> 2;
    const int gm = blockIdx.x * TILE_M;
    const int n0 = blockIdx.y * 64;

    float acc[3][2][2][4];
    gemm_core(g_Xr, g_Wir, smf, sb, gm, n0, tid, lane, warp_m, wn, acc);

    const int rl = lane >> 2, cl = (lane & 3) * 2;
    const int colb = wn * 16;
#pragma unroll
    for (int mt = 0; mt < 2; mt++)
#pragma unroll
        for (int rp = 0; rp < 2; rp++) {
            int row = warp_m * 32 + mt * 16 + rp * 8 + rl;
            float* Gp = &g_G[(size_t)(gm + row) * G3];
#pragma unroll
            for (int g = 0; g < 3; g++)
#pragma unroll
                for (int nt = 0; nt < 2; nt++) {
                    int col = n0 + colb + nt * 8 + cl;
                    float2 bv = *(const float2*)&bih[g * H_DIM + col];
                    float2 o;
                    o.x = acc[g][mt][nt][rp * 2 + 0] + bv.x;
                    o.y = acc[g][mt][nt][rp * 2 + 1] + bv.y;
                    *(float2*)&Gp[g * H_DIM + col] = o;
                }
        }
}

// ---------------------------------------------------------------------------
// fused steps: t=0 elementwise, then t=1..15 GEMM+GRU, cluster(1,4) sync
// between steps (the 4 N-tile CTAs of one M-tile exchange H columns).
// ---------------------------------------------------------------------------
__global__ __launch_bounds__(THREADS, 1) __cluster_dims__(1, 4, 1)
void fused_kernel(const float* __restrict__ bih,
                  const float* __restrict__ bhh,
                  float* __restrict__ fin)
{
    extern __shared__ float smf[];
    const uint32_t sb = smem_u32(smf);
    const int tid = threadIdx.x;
    const int lane = tid & 31, wid = tid >> 5;
    const int warp_m = wid & 3, wn = wid >> 2;
    const int gm = blockIdx.x * TILE_M;
    const int n0 = blockIdx.y * 64;

    // ---- t = 0: h starts at zero -> pure elementwise ----
    for (int j = tid; j < TILE_M * 64; j += THREADS) {
        int r = j >> 6, cloc = j & 63;
        int grow = gm + r, col = n0 + cloc;
        int l = grow & (L_DIM - 1);
        int src = l - (KWIN - 1);
        float gir, giz, gin;
        if (src >= 0) {
            const float* Gp = &g_G[(size_t)(grow - l + src) * G3 + col];
            gir = Gp[0]; giz = Gp[H_DIM]; gin = Gp[2 * H_DIM];
        } else {
            gir = bih[col]; giz = bih[col + H_DIM]; gin = bih[col + 2 * H_DIM];
        }
        float rr = sigm(gir + bhh[col]);
        float zz = sigm(giz + bhh[col + H_DIM]);
        float nn = tanh_apx(gin + rr * bhh[col + 2 * H_DIM]);
        float h0 = (1.0f - zz) * nn;
        g_H[0][(size_t)grow * H_DIM + col] = h0;
        g_Ht[0][(size_t)grow * H_DIM + col] = rna_tf32(h0);
    }
    CLUSTER_SYNC();

    const int rl = lane >> 2, cl = (lane & 3) * 2;
    const int colb = wn * 16;

#pragma unroll 1
    for (int t = 1; t < KWIN; t++) {
        const int in_idx = (t - 1) & 1;
        float acc[3][2][2][4];
        gemm_core(g_Ht[in_idx], g_Whr, smf, sb, gm, n0, tid, lane, warp_m, wn, acc);

        const float* __restrict__ Hi = g_H[in_idx];
        const bool last = (t == KWIN - 1);
        float* __restrict__ Ho  = last ? fin : g_H[in_idx ^ 1];
        float* __restrict__ Hot = g_Ht[in_idx ^ 1];

#pragma unroll
        for (int mt = 0; mt < 2; mt++)
#pragma unroll
            for (int rp = 0; rp < 2; rp++) {
                int grow = gm + warp_m * 32 + mt * 16 + rp * 8 + rl;
                int l = grow & (L_DIM - 1);
                int src = l + t - (KWIN - 1);
                const float* Gp = (src >= 0) ? &g_G[(size_t)(grow - l + src) * G3] : bih;
                const float* Hir = &Hi[(size_t)grow * H_DIM];
#pragma unroll
                for (int nt = 0; nt < 2; nt++) {
                    int col = n0 + colb + nt * 8 + cl;
                    float2 gr = *(const float2*)&Gp[col];
                    float2 gz = *(const float2*)&Gp[H_DIM + col];
                    float2 gn = *(const float2*)&Gp[2 * H_DIM + col];
                    float2 br = *(const float2*)&bhh[col];
                    float2 bz = *(const float2*)&bhh[H_DIM + col];
                    float2 bn = *(const float2*)&bhh[2 * H_DIM + col];
                    float2 h  = *(const float2*)&Hir[col];
                    float2 o;
                    {
                        float r  = sigm(gr.x + acc[0][mt][nt][rp * 2] + br.x);
                        float z  = sigm(gz.x + acc[1][mt][nt][rp * 2] + bz.x);
                        float nn = tanh_apx(gn.x + r * (acc[2][mt][nt][rp * 2] + bn.x));
                        o.x = (1.0f - z) * nn + z * h.x;
                    }
                    {
                        float r  = sigm(gr.y + acc[0][mt][nt][rp * 2 + 1] + br.y);
                        float z  = sigm(gz.y + acc[1][mt][nt][rp * 2 + 1] + bz.y);
                        float nn = tanh_apx(gn.y + r * (acc[2][mt][nt][rp * 2 + 1] + bn.y));
                        o.y = (1.0f - z) * nn + z * h.y;
                    }
                    *(float2*)&Ho[(size_t)grow * H_DIM + col] = o;
                    if (!last) {
                        float2 ot = make_float2(rna_tf32(o.x), rna_tf32(o.y));
                        *(float2*)&Hot[(size_t)grow * H_DIM + col] = ot;
                    }
                }
            }
        if (!last) CLUSTER_SYNC();
    }
}

// ---------------------------------------------------------------------------
// Launch: prep -> proj -> fused (3 launches total)
// ---------------------------------------------------------------------------
extern "C" void kernel_launch(void* const* d_in, const int* in_sizes, int n_in,
                              void* d_out, int out_size)
{
    const float* x   = (const float*)d_in[0];
    const float* Wih = (const float*)d_in[1];
    const float* Whh = (const float*)d_in[2];
    const float* bih = (const float*)d_in[3];
    const float* bhh = (const float*)d_in[4];
    float* out = (float*)d_out;

    cudaFuncSetAttribute(proj_kernel,  cudaFuncAttributeMaxDynamicSharedMemorySize, SMEM_BYTES);
    cudaFuncSetAttribute(fused_kernel, cudaFuncAttributeMaxDynamicSharedMemorySize, SMEM_BYTES);

    prep_kernel<<<(R_TOTAL * KDIM + 255) / 256, 256>>>(x, Wih, Whh);
    dim3 grid(R_TOTAL / TILE_M, H_DIM / 64);   // (128, 4)
    proj_kernel<<<grid, THREADS, SMEM_BYTES>>>(bih);
    fused_kernel<<<grid, THREADS, SMEM_BYTES>>>(bih, bhh, out);
}

// round 8
// speedup vs baseline: 1.4924x; 1.4924x over previous
#include <cuda_runtime.h>
#include <cuda_fp16.h>
#include <cstdint>

// Problem dims (fixed)
#define L_DIM   1024
#define H_DIM   256
#define KWIN    16
#define R_TOTAL 16384
#define G3      768
#define KDIM    256

// Tiling
#define TILE_M  128
#define NTOT    192                 // 3 gates x 64 cols
#define BK      64
#define NCHUNK  (KDIM / BK)         // 4
#define THREADS 512

// Smem (halves), padded stride 72 -> conflict-free ldmatrix (rows 4 banks apart)
#define AS      72
#define BS      72
#define ABUF    (TILE_M * AS)       // 9216 halves
#define BBUF    (NTOT * BS)         // 13824 halves
#define BUFF    (ABUF + BBUF)       // 23040 halves
#define NBUF    3
#define SMEM_BYTES (NBUF * BUFF * 2)   // 138240 B

// Scratch (allocation-free rule: device globals)
__device__ float  g_G[R_TOTAL * G3];          // input projections incl. b_ih (f32)
__device__ float  g_H[2][R_TOTAL * H_DIM];    // exact hidden state (ping-pong, f32)
__device__ __half g_Hh[2][R_TOTAL * H_DIM];   // fp16 hidden state (GEMM A operand)
__device__ __half g_Xh[R_TOTAL * KDIM];       // fp16 x
__device__ __half g_Wih_h[G3 * KDIM];         // fp16 W_ih
__device__ __half g_Whh_h[G3 * KDIM];         // fp16 W_hh

// ---------------------------------------------------------------------------
// helpers
// ---------------------------------------------------------------------------
__device__ __forceinline__ uint32_t smem_u32(const void* p) {
    uint32_t a;
    asm("{ .reg .u64 t; cvta.to.shared.u64 t, %1; cvt.u32.u64 %0, t; }" : "=r"(a) : "l"(p));
    return a;
}
__device__ __forceinline__ float tanh_apx(float x) {
    float y; asm("tanh.approx.f32 %0, %1;" : "=f"(y) : "f"(x)); return y;
}
__device__ __forceinline__ float sigm(float x) {
    return fmaf(tanh_apx(0.5f * x), 0.5f, 0.5f);
}

#define CP_ASYNC16(dst, src) \
    asm volatile("cp.async.cg.shared.global [%0], [%1], 16;" :: "r"(dst), "l"(src) : "memory")
#define CP_COMMIT() asm volatile("cp.async.commit_group;" ::: "memory")
#define CP_WAIT(n)  asm volatile("cp.async.wait_group %0;" :: "n"(n) : "memory")

#define LDSM_X4(r0, r1, r2, r3, addr)                                        \
    asm volatile("ldmatrix.sync.aligned.m8n8.x4.shared.b16 {%0,%1,%2,%3}, [%4];" \
        : "=r"(r0), "=r"(r1), "=r"(r2), "=r"(r3) : "r"(addr))

__device__ __forceinline__ void mma_f16(float* d, const uint32_t* a, uint32_t b0, uint32_t b1) {
    asm volatile(
        "mma.sync.aligned.m16n8k16.row.col.f32.f16.f16.f32 "
        "{%0,%1,%2,%3}, {%4,%5,%6,%7}, {%8,%9}, {%0,%1,%2,%3};"
        : "+f"(d[0]), "+f"(d[1]), "+f"(d[2]), "+f"(d[3])
        : "r"(a[0]), "r"(a[1]), "r"(a[2]), "r"(a[3]), "r"(b0), "r"(b1));
}

// ---------------------------------------------------------------------------
// GEMM mainloop: acc[3][2][2][4] += A[gm:gm+128, :256] x W[3x(n0:n0+64), :256]^T
// fp16 operands, f32 accum. Triple-buffered cp.async, 1 barrier per BK=64 chunk.
// ---------------------------------------------------------------------------
__device__ __forceinline__ void gemm_core(
    const __half* __restrict__ A, const __half* __restrict__ W,
    const __half* __restrict__ smf, uint32_t sb,
    int gm, int n0, int tid, int lane, int warp_m, int wn,
    float acc[3][2][2][4])
{
#pragma unroll
    for (int g = 0; g < 3; g++)
#pragma unroll
        for (int mt = 0; mt < 2; mt++)
#pragma unroll
            for (int nt = 0; nt < 2; nt++)
#pragma unroll
                for (int e = 0; e < 4; e++) acc[g][mt][nt][e] = 0.0f;

    auto issue = [&](int k0, int buf) {
        const uint32_t abase = sb + buf * (BUFF * 2);
#pragma unroll
        for (int i = 0; i < 2; i++) {                 // A: 1024 x 16B (8 halves)
            int j = tid + i * THREADS;
            int row = j >> 3, kv = (j & 7) << 3;
            CP_ASYNC16(abase + (row * AS + kv) * 2,
                       &A[(size_t)(gm + row) * KDIM + k0 + kv]);
        }
        const uint32_t bbase = abase + ABUF * 2;
#pragma unroll
        for (int i = 0; i < 3; i++) {                 // B: 1536 x 16B
            int j = tid + i * THREADS;
            int row = j >> 3, kv = (j & 7) << 3;      // row = g*64 + nloc
            int g = row >> 6, nl = row & 63;
            CP_ASYNC16(bbase + (row * BS + kv) * 2,
                       &W[(size_t)(g * H_DIM + n0 + nl) * KDIM + k0 + kv]);
        }
        CP_COMMIT();
    };

    // lane-derived ldmatrix address components
    const int lr8  = lane & 7;
    const int lbit = (lane >> 3) & 1;
    const int lhi  = lane >> 4;

    issue(0, 0);
    issue(BK, 1);
#pragma unroll 1
    for (int c = 0; c < NCHUNK; c++) {
        if (c == NCHUNK - 1) { CP_WAIT(0); } else { CP_WAIT(1); }
        __syncthreads();
        if (c + 2 < NCHUNK) issue((c + 2) * BK, (c + 2) % 3);

        const uint32_t sA = sb + (c % 3) * (BUFF * 2);
        const uint32_t sB = sA + ABUF * 2;
#pragma unroll
        for (int ks = 0; ks < 4; ks++) {
            const int kk = ks * 16;
            // A fragments: x4 per m16 tile; tiles (m0,k0)(m8,k0)(m0,k8)(m8,k8)
            uint32_t a[2][4];
#pragma unroll
            for (int mt = 0; mt < 2; mt++) {
                int row = warp_m * 32 + mt * 16 + lr8 + 8 * lbit;
                int col = kk + 8 * lhi;
                LDSM_X4(a[mt][0], a[mt][1], a[mt][2], a[mt][3],
                        sA + (row * AS + col) * 2);
            }
            // B fragments: x4 per gate covers nt=0,1; tiles (n0,k0)(n0,k8)(n8,k0)(n8,k8)
#pragma unroll
            for (int g = 0; g < 3; g++) {
                uint32_t b[4];
                int row = g * 64 + wn * 16 + lr8 + 8 * lhi;
                int col = kk + 8 * lbit;
                LDSM_X4(b[0], b[1], b[2], b[3], sB + (row * BS + col) * 2);
#pragma unroll
                for (int mt = 0; mt < 2; mt++) {
                    mma_f16(acc[g][mt][0], a[mt], b[0], b[1]);
                    mma_f16(acc[g][mt][1], a[mt], b[2], b[3]);
                }
            }
        }
    }
}

// ---------------------------------------------------------------------------
// prep: convert x, W_ih, W_hh to fp16 (RN)
// ---------------------------------------------------------------------------
__global__ __launch_bounds__(256) void prep_kernel(
    const float* __restrict__ x,
    const float* __restrict__ Wih,
    const float* __restrict__ Whh)
{
    int i = blockIdx.x * 256 + threadIdx.x;
    if (i < R_TOTAL * KDIM) g_Xh[i] = __float2half(x[i]);
    if (i < G3 * KDIM) {
        g_Wih_h[i] = __float2half(Wih[i]);
        g_Whh_h[i] = __float2half(Whh[i]);
    }
}

// ---------------------------------------------------------------------------
// Unified GEMM kernel.
// mode==0: proj (A=g_Xh, W=W_ih, out = acc + b_ih -> g_G)
// mode==t: step (A=g_Hh[in_idx], W=W_hh, GRU update -> g_H/g_Hh[in_idx^1] or fin)
// ---------------------------------------------------------------------------
__global__ __launch_bounds__(THREADS, 1) void gemm3_kernel(
    const float* __restrict__ bih,
    const float* __restrict__ bhh,
    int mode, int in_idx, float* __restrict__ fin)
{
    extern __shared__ __half smf[];
    const uint32_t sb = smem_u32(smf);
    const int tid = threadIdx.x;
    const int lane = tid & 31, wid = tid >> 5;
    const int warp_m = wid & 3, wn = wid >> 2;
    const int gm = blockIdx.x * TILE_M;
    const int n0 = blockIdx.y * 64;

    const __half* __restrict__ A = (mode == 0) ? g_Xh : g_Hh[in_idx];
    const __half* __restrict__ W = (mode == 0) ? g_Wih_h : g_Whh_h;

    float acc[3][2][2][4];
    gemm_core(A, W, smf, sb, gm, n0, tid, lane, warp_m, wn, acc);

    const int rl = lane >> 2, cl = (lane & 3) * 2;
    const int colb = wn * 16;

    if (mode == 0) {
#pragma unroll
        for (int mt = 0; mt < 2; mt++)
#pragma unroll
            for (int rp = 0; rp < 2; rp++) {
                int row = warp_m * 32 + mt * 16 + rp * 8 + rl;
                float* Gp = &g_G[(size_t)(gm + row) * G3];
#pragma unroll
                for (int g = 0; g < 3; g++)
#pragma unroll
                    for (int nt = 0; nt < 2; nt++) {
                        int col = n0 + colb + nt * 8 + cl;
                        float2 bv = *(const float2*)&bih[g * H_DIM + col];
                        float2 o;
                        o.x = acc[g][mt][nt][rp * 2 + 0] + bv.x;
                        o.y = acc[g][mt][nt][rp * 2 + 1] + bv.y;
                        *(float2*)&Gp[g * H_DIM + col] = o;
                    }
            }
    } else {
        const float* __restrict__ Hi = g_H[in_idx];
        const bool last = (fin != nullptr);
        float*  __restrict__ Ho  = last ? fin : g_H[in_idx ^ 1];
        __half* __restrict__ Hoh = g_Hh[in_idx ^ 1];
#pragma unroll
        for (int mt = 0; mt < 2; mt++)
#pragma unroll
            for (int rp = 0; rp < 2; rp++) {
                int grow = gm + warp_m * 32 + mt * 16 + rp * 8 + rl;
                int l = grow & (L_DIM - 1);
                int src = l + mode - (KWIN - 1);
                const float* Gp = (src >= 0) ? &g_G[(size_t)(grow - l + src) * G3] : bih;
                const float* Hir = &Hi[(size_t)grow * H_DIM];
#pragma unroll
                for (int nt = 0; nt < 2; nt++) {
                    int col = n0 + colb + nt * 8 + cl;
                    float2 gr = *(const float2*)&Gp[col];
                    float2 gz = *(const float2*)&Gp[H_DIM + col];
                    float2 gn = *(const float2*)&Gp[2 * H_DIM + col];
                    float2 br = *(const float2*)&bhh[col];
                    float2 bz = *(const float2*)&bhh[H_DIM + col];
                    float2 bn = *(const float2*)&bhh[2 * H_DIM + col];
                    float2 h  = *(const float2*)&Hir[col];
                    float2 o;
                    {
                        float r  = sigm(gr.x + acc[0][mt][nt][rp * 2] + br.x);
                        float z  = sigm(gz.x + acc[1][mt][nt][rp * 2] + bz.x);
                        float nn = tanh_apx(gn.x + r * (acc[2][mt][nt][rp * 2] + bn.x));
                        o.x = (1.0f - z) * nn + z * h.x;
                    }
                    {
                        float r  = sigm(gr.y + acc[0][mt][nt][rp * 2 + 1] + br.y);
                        float z  = sigm(gz.y + acc[1][mt][nt][rp * 2 + 1] + bz.y);
                        float nn = tanh_apx(gn.y + r * (acc[2][mt][nt][rp * 2 + 1] + bn.y));
                        o.y = (1.0f - z) * nn + z * h.y;
                    }
                    *(float2*)&Ho[(size_t)grow * H_DIM + col] = o;
                    if (!last)
                        *(__half2*)&Hoh[(size_t)grow * H_DIM + col] = __float22half2_rn(o);
                }
            }
    }
}

// ---------------------------------------------------------------------------
// Window step t=0 (h=0, pure elementwise)
// ---------------------------------------------------------------------------
__global__ __launch_bounds__(256) void step0_kernel(
    const float* __restrict__ bih, const float* __restrict__ bhh)
{
    const int row = blockIdx.x;
    const int col = threadIdx.x;
    const int l = row & (L_DIM - 1);
    const int src = l - (KWIN - 1);

    float gir, giz, gin;
    if (src >= 0) {
        const float* Gp = &g_G[(size_t)(row - l + src) * G3 + col];
        gir = Gp[0]; giz = Gp[H_DIM]; gin = Gp[2 * H_DIM];
    } else {
        gir = bih[col]; giz = bih[col + H_DIM]; gin = bih[col + 2 * H_DIM];
    }
    float r  = sigm(gir + bhh[col]);
    float z  = sigm(giz + bhh[col + H_DIM]);
    float nn = tanh_apx(gin + r * bhh[col + 2 * H_DIM]);
    float h0 = (1.0f - z) * nn;
    g_H[0][(size_t)row * H_DIM + col] = h0;
    g_Hh[0][(size_t)row * H_DIM + col] = __float2half(h0);
}

// ---------------------------------------------------------------------------
// Launch: prep -> proj -> step0 -> 15 x fused mma step (last writes d_out)
// ---------------------------------------------------------------------------
extern "C" void kernel_launch(void* const* d_in, const int* in_sizes, int n_in,
                              void* d_out, int out_size)
{
    const float* x   = (const float*)d_in[0];
    const float* Wih = (const float*)d_in[1];
    const float* Whh = (const float*)d_in[2];
    const float* bih = (const float*)d_in[3];
    const float* bhh = (const float*)d_in[4];
    float* out = (float*)d_out;

    cudaFuncSetAttribute(gemm3_kernel, cudaFuncAttributeMaxDynamicSharedMemorySize, SMEM_BYTES);

    prep_kernel<<<(R_TOTAL * KDIM + 255) / 256, 256>>>(x, Wih, Whh);
    dim3 grid(R_TOTAL / TILE_M, H_DIM / 64);   // (128, 4)
    gemm3_kernel<<<grid, THREADS, SMEM_BYTES>>>(bih, bhh, 0, 0, nullptr);
    step0_kernel<<<R_TOTAL, 256>>>(bih, bhh);
    for (int t = 1; t < KWIN; t++) {
        int in_idx = (t - 1) & 1;
        float* fin = (t == KWIN - 1) ? out : nullptr;
        gemm3_kernel<<<grid, THREADS, SMEM_BYTES>>>(bih, bhh, t, in_idx, fin);
    }
}

// round 9
// speedup vs baseline: 1.6357x; 1.0960x over previous
#include <cuda_runtime.h>
#include <cuda_fp16.h>
#include <cstdint>

// Problem dims (fixed)
#define L_DIM   1024
#define H_DIM   256
#define KWIN    16
#define R_TOTAL 16384
#define G3      768
#define KDIM    256

// Tiling: M=64 x (3 gates x 64 cols), 256 threads, 2 CTAs/SM
#define TILE_M  64
#define NTOT    192
#define BK      64
#define NCHUNK  (KDIM / BK)         // 4
#define THREADS 256

// Smem (halves), padded stride 72 -> conflict-free ldmatrix
#define AS      72
#define BS      72
#define ABUF    (TILE_M * AS)       // 4608 halves
#define BBUF    (NTOT * BS)         // 13824 halves
#define BUFF    (ABUF + BBUF)       // 18432 halves
#define NBUF    3
#define SMEM_BYTES (NBUF * BUFF * 2)   // 110592 B -> 2 CTAs/SM

// Scratch (allocation-free rule: device globals)
__device__ float  g_G[R_TOTAL * G3];          // input projections incl. b_ih (f32)
__device__ float  g_H[2][R_TOTAL * H_DIM];    // exact hidden state (ping-pong, f32)
__device__ __half g_Hh[2][R_TOTAL * H_DIM];   // fp16 hidden state (GEMM A operand)
__device__ __half g_Xh[R_TOTAL * KDIM];       // fp16 x
__device__ __half g_Wih_h[G3 * KDIM];         // fp16 W_ih
__device__ __half g_Whh_h[G3 * KDIM];         // fp16 W_hh

// ---------------------------------------------------------------------------
// helpers
// ---------------------------------------------------------------------------
__device__ __forceinline__ uint32_t smem_u32(const void* p) {
    uint32_t a;
    asm("{ .reg .u64 t; cvta.to.shared.u64 t, %1; cvt.u32.u64 %0, t; }" : "=r"(a) : "l"(p));
    return a;
}
__device__ __forceinline__ float tanh_apx(float x) {
    float y; asm("tanh.approx.f32 %0, %1;" : "=f"(y) : "f"(x)); return y;
}
__device__ __forceinline__ float sigm(float x) {
    return fmaf(tanh_apx(0.5f * x), 0.5f, 0.5f);
}

#define CP_ASYNC16(dst, src) \
    asm volatile("cp.async.cg.shared.global [%0], [%1], 16;" :: "r"(dst), "l"(src) : "memory")
#define CP_COMMIT() asm volatile("cp.async.commit_group;" ::: "memory")
#define CP_WAIT(n)  asm volatile("cp.async.wait_group %0;" :: "n"(n) : "memory")

#define LDSM_X4(r0, r1, r2, r3, addr)                                        \
    asm volatile("ldmatrix.sync.aligned.m8n8.x4.shared.b16 {%0,%1,%2,%3}, [%4];" \
        : "=r"(r0), "=r"(r1), "=r"(r2), "=r"(r3) : "r"(addr))

__device__ __forceinline__ void mma_f16(float* d, const uint32_t* a, uint32_t b0, uint32_t b1) {
    asm volatile(
        "mma.sync.aligned.m16n8k16.row.col.f32.f16.f16.f32 "
        "{%0,%1,%2,%3}, {%4,%5,%6,%7}, {%8,%9}, {%0,%1,%2,%3};"
        : "+f"(d[0]), "+f"(d[1]), "+f"(d[2]), "+f"(d[3])
        : "r"(a[0]), "r"(a[1]), "r"(a[2]), "r"(a[3]), "r"(b0), "r"(b1));
}

// ---------------------------------------------------------------------------
// GEMM mainloop: acc[3][2][2][4] += A[gm:gm+64, :256] x W[3x(n0:n0+64), :256]^T
// fp16 operands, f32 accum. Triple-buffered cp.async, 1 barrier per BK=64 chunk.
// Warp layout: warp_m = wid&1 (2 x m32), wn = wid>>1 (4 x n16 per gate).
// ---------------------------------------------------------------------------
__device__ __forceinline__ void gemm_core(
    const __half* __restrict__ A, const __half* __restrict__ W,
    const __half* __restrict__ smf, uint32_t sb,
    int gm, int n0, int tid, int lane, int warp_m, int wn,
    float acc[3][2][2][4])
{
#pragma unroll
    for (int g = 0; g < 3; g++)
#pragma unroll
        for (int mt = 0; mt < 2; mt++)
#pragma unroll
            for (int nt = 0; nt < 2; nt++)
#pragma unroll
                for (int e = 0; e < 4; e++) acc[g][mt][nt][e] = 0.0f;

    auto issue = [&](int k0, int buf) {
        const uint32_t abase = sb + buf * (BUFF * 2);
#pragma unroll
        for (int i = 0; i < 2; i++) {                 // A: 512 x 16B (8 halves)
            int j = tid + i * THREADS;
            int row = j >> 3, kv = (j & 7) << 3;
            CP_ASYNC16(abase + (row * AS + kv) * 2,
                       &A[(size_t)(gm + row) * KDIM + k0 + kv]);
        }
        const uint32_t bbase = abase + ABUF * 2;
#pragma unroll
        for (int i = 0; i < 6; i++) {                 // B: 1536 x 16B
            int j = tid + i * THREADS;
            int row = j >> 3, kv = (j & 7) << 3;      // row = g*64 + nloc
            int g = row >> 6, nl = row & 63;
            CP_ASYNC16(bbase + (row * BS + kv) * 2,
                       &W[(size_t)(g * H_DIM + n0 + nl) * KDIM + k0 + kv]);
        }
        CP_COMMIT();
    };

    const int lr8  = lane & 7;
    const int lbit = (lane >> 3) & 1;
    const int lhi  = lane >> 4;

    issue(0, 0);
    issue(BK, 1);
#pragma unroll 1
    for (int c = 0; c < NCHUNK; c++) {
        if (c == NCHUNK - 1) { CP_WAIT(0); } else { CP_WAIT(1); }
        __syncthreads();
        if (c + 2 < NCHUNK) issue((c + 2) * BK, (c + 2) % 3);

        const uint32_t sA = sb + (c % 3) * (BUFF * 2);
        const uint32_t sB = sA + ABUF * 2;
#pragma unroll
        for (int ks = 0; ks < 4; ks++) {
            const int kk = ks * 16;
            uint32_t a[2][4];
#pragma unroll
            for (int mt = 0; mt < 2; mt++) {
                int row = warp_m * 32 + mt * 16 + lr8 + 8 * lbit;
                int col = kk + 8 * lhi;
                LDSM_X4(a[mt][0], a[mt][1], a[mt][2], a[mt][3],
                        sA + (row * AS + col) * 2);
            }
#pragma unroll
            for (int g = 0; g < 3; g++) {
                uint32_t b[4];
                int row = g * 64 + wn * 16 + lr8 + 8 * lhi;
                int col = kk + 8 * lbit;
                LDSM_X4(b[0], b[1], b[2], b[3], sB + (row * BS + col) * 2);
#pragma unroll
                for (int mt = 0; mt < 2; mt++) {
                    mma_f16(acc[g][mt][0], a[mt], b[0], b[1]);
                    mma_f16(acc[g][mt][1], a[mt], b[2], b[3]);
                }
            }
        }
    }
}

// ---------------------------------------------------------------------------
// prep: convert x, W_ih, W_hh to fp16 (RN)
// ---------------------------------------------------------------------------
__global__ __launch_bounds__(256) void prep_kernel(
    const float* __restrict__ x,
    const float* __restrict__ Wih,
    const float* __restrict__ Whh)
{
    int i = blockIdx.x * 256 + threadIdx.x;
    if (i < R_TOTAL * KDIM) g_Xh[i] = __float2half(x[i]);
    if (i < G3 * KDIM) {
        g_Wih_h[i] = __float2half(Wih[i]);
        g_Whh_h[i] = __float2half(Whh[i]);
    }
}

// ---------------------------------------------------------------------------
// Unified GEMM kernel.
// mode==0: proj (A=g_Xh, W=W_ih, out = acc + b_ih -> g_G)
// mode==t: step (A=g_Hh[in_idx], W=W_hh, GRU update -> g_H/g_Hh[in_idx^1] or fin)
// ---------------------------------------------------------------------------
__global__ __launch_bounds__(THREADS, 2) void gemm3_kernel(
    const float* __restrict__ bih,
    const float* __restrict__ bhh,
    int mode, int in_idx, float* __restrict__ fin)
{
    extern __shared__ __half smf[];
    const uint32_t sb = smem_u32(smf);
    const int tid = threadIdx.x;
    const int lane = tid & 31, wid = tid >> 5;
    const int warp_m = wid & 1, wn = wid >> 1;
    const int gm = blockIdx.x * TILE_M;
    const int n0 = blockIdx.y * 64;

    const __half* __restrict__ A = (mode == 0) ? g_Xh : g_Hh[in_idx];
    const __half* __restrict__ W = (mode == 0) ? g_Wih_h : g_Whh_h;

    float acc[3][2][2][4];
    gemm_core(A, W, smf, sb, gm, n0, tid, lane, warp_m, wn, acc);

    const int rl = lane >> 2, cl = (lane & 3) * 2;
    const int colb = wn * 16;

    if (mode == 0) {
#pragma unroll
        for (int mt = 0; mt < 2; mt++)
#pragma unroll
            for (int rp = 0; rp < 2; rp++) {
                int row = warp_m * 32 + mt * 16 + rp * 8 + rl;
                float* Gp = &g_G[(size_t)(gm + row) * G3];
#pragma unroll
                for (int g = 0; g < 3; g++)
#pragma unroll
                    for (int nt = 0; nt < 2; nt++) {
                        int col = n0 + colb + nt * 8 + cl;
                        float2 bv = *(const float2*)&bih[g * H_DIM + col];
                        float2 o;
                        o.x = acc[g][mt][nt][rp * 2 + 0] + bv.x;
                        o.y = acc[g][mt][nt][rp * 2 + 1] + bv.y;
                        *(float2*)&Gp[g * H_DIM + col] = o;
                    }
            }
    } else {
        const float* __restrict__ Hi = g_H[in_idx];
        const bool last = (fin != nullptr);
        float*  __restrict__ Ho  = last ? fin : g_H[in_idx ^ 1];
        __half* __restrict__ Hoh = g_Hh[in_idx ^ 1];
#pragma unroll
        for (int mt = 0; mt < 2; mt++)
#pragma unroll
            for (int rp = 0; rp < 2; rp++) {
                int grow = gm + warp_m * 32 + mt * 16 + rp * 8 + rl;
                int l = grow & (L_DIM - 1);
                int src = l + mode - (KWIN - 1);
                const float* Gp = (src >= 0) ? &g_G[(size_t)(grow - l + src) * G3] : bih;
                const float* Hir = &Hi[(size_t)grow * H_DIM];
#pragma unroll
                for (int nt = 0; nt < 2; nt++) {
                    int col = n0 + colb + nt * 8 + cl;
                    float2 gr = *(const float2*)&Gp[col];
                    float2 gz = *(const float2*)&Gp[H_DIM + col];
                    float2 gn = *(const float2*)&Gp[2 * H_DIM + col];
                    float2 br = *(const float2*)&bhh[col];
                    float2 bz = *(const float2*)&bhh[H_DIM + col];
                    float2 bn = *(const float2*)&bhh[2 * H_DIM + col];
                    float2 h  = *(const float2*)&Hir[col];
                    float2 o;
                    {
                        float r  = sigm(gr.x + acc[0][mt][nt][rp * 2] + br.x);
                        float z  = sigm(gz.x + acc[1][mt][nt][rp * 2] + bz.x);
                        float nn = tanh_apx(gn.x + r * (acc[2][mt][nt][rp * 2] + bn.x));
                        o.x = (1.0f - z) * nn + z * h.x;
                    }
                    {
                        float r  = sigm(gr.y + acc[0][mt][nt][rp * 2 + 1] + br.y);
                        float z  = sigm(gz.y + acc[1][mt][nt][rp * 2 + 1] + bz.y);
                        float nn = tanh_apx(gn.y + r * (acc[2][mt][nt][rp * 2 + 1] + bn.y));
                        o.y = (1.0f - z) * nn + z * h.y;
                    }
                    *(float2*)&Ho[(size_t)grow * H_DIM + col] = o;
                    if (!last)
                        *(__half2*)&Hoh[(size_t)grow * H_DIM + col] = __float22half2_rn(o);
                }
            }
    }
}

// ---------------------------------------------------------------------------
// Window step t=0 (h=0, pure elementwise)
// ---------------------------------------------------------------------------
__global__ __launch_bounds__(256) void step0_kernel(
    const float* __restrict__ bih, const float* __restrict__ bhh)
{
    const int row = blockIdx.x;
    const int col = threadIdx.x;
    const int l = row & (L_DIM - 1);
    const int src = l - (KWIN - 1);

    float gir, giz, gin;
    if (src >= 0) {
        const float* Gp = &g_G[(size_t)(row - l + src) * G3 + col];
        gir = Gp[0]; giz = Gp[H_DIM]; gin = Gp[2 * H_DIM];
    } else {
        gir = bih[col]; giz = bih[col + H_DIM]; gin = bih[col + 2 * H_DIM];
    }
    float r  = sigm(gir + bhh[col]);
    float z  = sigm(giz + bhh[col + H_DIM]);
    float nn = tanh_apx(gin + r * bhh[col + 2 * H_DIM]);
    float h0 = (1.0f - z) * nn;
    g_H[0][(size_t)row * H_DIM + col] = h0;
    g_Hh[0][(size_t)row * H_DIM + col] = __float2half(h0);
}

// ---------------------------------------------------------------------------
// Launch: prep -> proj -> step0 -> 15 x fused mma step (last writes d_out)
// ---------------------------------------------------------------------------
extern "C" void kernel_launch(void* const* d_in, const int* in_sizes, int n_in,
                              void* d_out, int out_size)
{
    const float* x   = (const float*)d_in[0];
    const float* Wih = (const float*)d_in[1];
    const float* Whh = (const float*)d_in[2];
    const float* bih = (const float*)d_in[3];
    const float* bhh = (const float*)d_in[4];
    float* out = (float*)d_out;

    cudaFuncSetAttribute(gemm3_kernel, cudaFuncAttributeMaxDynamicSharedMemorySize, SMEM_BYTES);

    prep_kernel<<<(R_TOTAL * KDIM + 255) / 256, 256>>>(x, Wih, Whh);
    dim3 grid(R_TOTAL / TILE_M, H_DIM / 64);   // (256, 4)
    gemm3_kernel<<<grid, THREADS, SMEM_BYTES>>>(bih, bhh, 0, 0, nullptr);
    step0_kernel<<<R_TOTAL, 256>>>(bih, bhh);
    for (int t = 1; t < KWIN; t++) {
        int in_idx = (t - 1) & 1;
        float* fin = (t == KWIN - 1) ? out : nullptr;
        gemm3_kernel<<<grid, THREADS, SMEM_BYTES>>>(bih, bhh, t, in_idx, fin);
    }
}

// round 10
// speedup vs baseline: 1.8009x; 1.1010x over previous
#include <cuda_runtime.h>
#include <cuda_fp16.h>
#include <cstdint>

// Problem dims (fixed)
#define L_DIM   1024
#define H_DIM   256
#define KWIN    16
#define R_TOTAL 16384
#define G3      768
#define KDIM    256

// Tiling: M=64 x (3 gates x 64 cols), 256 threads, 2 CTAs/SM
#define TILE_M  64
#define NTOT    192
#define BK      64
#define NCHUNK  (KDIM / BK)         // 4
#define THREADS 256

// Smem (halves), padded stride 72 -> conflict-free ldmatrix
#define AS      72
#define BS      72
#define ABUF    (TILE_M * AS)       // 4608 halves
#define BBUF    (NTOT * BS)         // 13824 halves
#define BUFF    (ABUF + BBUF)       // 18432 halves
#define NBUF    3
#define SMEM_BYTES (NBUF * BUFF * 2)   // 110592 B -> 2 CTAs/SM

// Epilogue staging regions (byte offsets into the same dynamic smem; reused
// after the mainloop ring is drained). Strides padded for bank spread.
#define SG_OFF  0                   // G staged: 64 rows x 204 f32 stride (816B)
#define SH_OFF  52224               // H staged: 64 rows x 68 f32 stride (272B)
#define SO_OFF  69632               // out f32:  64 rows x 68 f32 stride (272B)
#define SOH_OFF 87040               // out fp16: 64 rows x 72 half stride (144B)
// total 96256 <= SMEM_BYTES

// Scratch (allocation-free rule: device globals)
__device__ float  g_G[R_TOTAL * G3];          // input projections incl. b_ih (f32)
__device__ float  g_H[2][R_TOTAL * H_DIM];    // exact hidden state (ping-pong, f32)
__device__ __half g_Hh[2][R_TOTAL * H_DIM];   // fp16 hidden state (GEMM A operand)
__device__ __half g_Xh[R_TOTAL * KDIM];       // fp16 x
__device__ __half g_Wih_h[G3 * KDIM];         // fp16 W_ih
__device__ __half g_Whh_h[G3 * KDIM];         // fp16 W_hh

// ---------------------------------------------------------------------------
// helpers
// ---------------------------------------------------------------------------
__device__ __forceinline__ uint32_t smem_u32(const void* p) {
    uint32_t a;
    asm("{ .reg .u64 t; cvta.to.shared.u64 t, %1; cvt.u32.u64 %0, t; }" : "=r"(a) : "l"(p));
    return a;
}
__device__ __forceinline__ float tanh_apx(float x) {
    float y; asm("tanh.approx.f32 %0, %1;" : "=f"(y) : "f"(x)); return y;
}
__device__ __forceinline__ float sigm(float x) {
    return fmaf(tanh_apx(0.5f * x), 0.5f, 0.5f);
}

#define CP_ASYNC16(dst, src) \
    asm volatile("cp.async.cg.shared.global [%0], [%1], 16;" :: "r"(dst), "l"(src) : "memory")
#define CP_COMMIT() asm volatile("cp.async.commit_group;" ::: "memory")
#define CP_WAIT(n)  asm volatile("cp.async.wait_group %0;" :: "n"(n) : "memory")

#define LDSM_X4(r0, r1, r2, r3, addr)                                        \
    asm volatile("ldmatrix.sync.aligned.m8n8.x4.shared.b16 {%0,%1,%2,%3}, [%4];" \
        : "=r"(r0), "=r"(r1), "=r"(r2), "=r"(r3) : "r"(addr))

__device__ __forceinline__ void mma_f16(float* d, const uint32_t* a, uint32_t b0, uint32_t b1) {
    asm volatile(
        "mma.sync.aligned.m16n8k16.row.col.f32.f16.f16.f32 "
        "{%0,%1,%2,%3}, {%4,%5,%6,%7}, {%8,%9}, {%0,%1,%2,%3};"
        : "+f"(d[0]), "+f"(d[1]), "+f"(d[2]), "+f"(d[3])
        : "r"(a[0]), "r"(a[1]), "r"(a[2]), "r"(a[3]), "r"(b0), "r"(b1));
}

// ---------------------------------------------------------------------------
// GEMM mainloop: acc[3][2][2][4] += A[gm:gm+64, :256] x W[3x(n0:n0+64), :256]^T
// ---------------------------------------------------------------------------
__device__ __forceinline__ void gemm_core(
    const __half* __restrict__ A, const __half* __restrict__ W,
    uint32_t sb,
    int gm, int n0, int tid, int lane, int warp_m, int wn,
    float acc[3][2][2][4])
{
#pragma unroll
    for (int g = 0; g < 3; g++)
#pragma unroll
        for (int mt = 0; mt < 2; mt++)
#pragma unroll
            for (int nt = 0; nt < 2; nt++)
#pragma unroll
                for (int e = 0; e < 4; e++) acc[g][mt][nt][e] = 0.0f;

    auto issue = [&](int k0, int buf) {
        const uint32_t abase = sb + buf * (BUFF * 2);
#pragma unroll
        for (int i = 0; i < 2; i++) {                 // A: 512 x 16B (8 halves)
            int j = tid + i * THREADS;
            int row = j >> 3, kv = (j & 7) << 3;
            CP_ASYNC16(abase + (row * AS + kv) * 2,
                       &A[(size_t)(gm + row) * KDIM + k0 + kv]);
        }
        const uint32_t bbase = abase + ABUF * 2;
#pragma unroll
        for (int i = 0; i < 6; i++) {                 // B: 1536 x 16B
            int j = tid + i * THREADS;
            int row = j >> 3, kv = (j & 7) << 3;      // row = g*64 + nloc
            int g = row >> 6, nl = row & 63;
            CP_ASYNC16(bbase + (row * BS + kv) * 2,
                       &W[(size_t)(g * H_DIM + n0 + nl) * KDIM + k0 + kv]);
        }
        CP_COMMIT();
    };

    const int lr8  = lane & 7;
    const int lbit = (lane >> 3) & 1;
    const int lhi  = lane >> 4;

    issue(0, 0);
    issue(BK, 1);
#pragma unroll 1
    for (int c = 0; c < NCHUNK; c++) {
        if (c == NCHUNK - 1) { CP_WAIT(0); } else { CP_WAIT(1); }
        __syncthreads();
        if (c + 2 < NCHUNK) issue((c + 2) * BK, (c + 2) % 3);

        const uint32_t sA = sb + (c % 3) * (BUFF * 2);
        const uint32_t sB = sA + ABUF * 2;
#pragma unroll
        for (int ks = 0; ks < 4; ks++) {
            const int kk = ks * 16;
            uint32_t a[2][4];
#pragma unroll
            for (int mt = 0; mt < 2; mt++) {
                int row = warp_m * 32 + mt * 16 + lr8 + 8 * lbit;
                int col = kk + 8 * lhi;
                LDSM_X4(a[mt][0], a[mt][1], a[mt][2], a[mt][3],
                        sA + (row * AS + col) * 2);
            }
#pragma unroll
            for (int g = 0; g < 3; g++) {
                uint32_t b[4];
                int row = g * 64 + wn * 16 + lr8 + 8 * lhi;
                int col = kk + 8 * lbit;
                LDSM_X4(b[0], b[1], b[2], b[3], sB + (row * BS + col) * 2);
#pragma unroll
                for (int mt = 0; mt < 2; mt++) {
                    mma_f16(acc[g][mt][0], a[mt], b[0], b[1]);
                    mma_f16(acc[g][mt][1], a[mt], b[2], b[3]);
                }
            }
        }
    }
}

// ---------------------------------------------------------------------------
// prep: convert x, W_ih, W_hh to fp16 (RN)
// ---------------------------------------------------------------------------
__global__ __launch_bounds__(256) void prep_kernel(
    const float* __restrict__ x,
    const float* __restrict__ Wih,
    const float* __restrict__ Whh)
{
    int i = blockIdx.x * 256 + threadIdx.x;
    if (i < R_TOTAL * KDIM) g_Xh[i] = __float2half(x[i]);
    if (i < G3 * KDIM) {
        g_Wih_h[i] = __float2half(Wih[i]);
        g_Whh_h[i] = __float2half(Whh[i]);
    }
}

// ---------------------------------------------------------------------------
// Unified GEMM kernel with smem-staged coalesced epilogue.
// mode==0: proj (A=g_Xh, W=W_ih, out = acc + b_ih -> g_G)
// mode==t: step (A=g_Hh[in_idx], W=W_hh, GRU update -> g_H/g_Hh[in_idx^1] or fin)
// ---------------------------------------------------------------------------
__global__ __launch_bounds__(THREADS, 2) void gemm3_kernel(
    const float* __restrict__ bih,
    const float* __restrict__ bhh,
    int mode, int in_idx, float* __restrict__ fin)
{
    extern __shared__ __half smf[];
    char* const smc = (char*)smf;
    const uint32_t sb = smem_u32(smf);
    const int tid = threadIdx.x;
    const int lane = tid & 31, wid = tid >> 5;
    const int warp_m = wid & 1, wn = wid >> 1;
    const int gm = blockIdx.x * TILE_M;
    const int n0 = blockIdx.y * 64;

    const __half* __restrict__ A = (mode == 0) ? g_Xh : g_Hh[in_idx];
    const __half* __restrict__ W = (mode == 0) ? g_Wih_h : g_Whh_h;

    float acc[3][2][2][4];
    gemm_core(A, W, sb, gm, n0, tid, lane, warp_m, wn, acc);

    __syncthreads();   // ring buffers now free for staging reuse

    const int rl = lane >> 2, cl = (lane & 3) * 2;
    const int colb = wn * 16;

    if (mode == 0) {
        // stage G = acc + b_ih into SG, then coalesced store
#pragma unroll
        for (int mt = 0; mt < 2; mt++)
#pragma unroll
            for (int rp = 0; rp < 2; rp++) {
                int rloc = warp_m * 32 + mt * 16 + rp * 8 + rl;
#pragma unroll
                for (int g = 0; g < 3; g++)
#pragma unroll
                    for (int nt = 0; nt < 2; nt++) {
                        int cloc = colb + nt * 8 + cl;
                        float2 bv = *(const float2*)&bih[g * H_DIM + n0 + cloc];
                        float2 o;
                        o.x = acc[g][mt][nt][rp * 2 + 0] + bv.x;
                        o.y = acc[g][mt][nt][rp * 2 + 1] + bv.y;
                        *(float2*)(smc + SG_OFF + rloc * 816 + (g * 64 + cloc) * 4) = o;
                    }
            }
        __syncthreads();
        for (int j = tid; j < 64 * 48; j += THREADS) {   // 48 float4 per row
            int r = j / 48, c2 = j % 48;
            int g = c2 >> 4, q = c2 & 15;
            float4 v = *(const float4*)(smc + SG_OFF + r * 816 + c2 * 16);
            *(float4*)&g_G[(size_t)(gm + r) * G3 + g * H_DIM + n0 + q * 4] = v;
        }
    } else {
        const int t0 = mode - (KWIN - 1);   // in [-14, 0]
        const float* __restrict__ Hi = g_H[in_idx];
        const bool last = (fin != nullptr);
        float*  __restrict__ Ho  = last ? fin : g_H[in_idx ^ 1];
        __half* __restrict__ Hoh = g_Hh[in_idx ^ 1];

        // --- stage G window (48 chunks/row) + H (16 chunks/row) via cp.async ---
        for (int j = tid; j < 64 * 64; j += THREADS) {
            int r = j >> 6, rem = j & 63;
            int grow = gm + r;
            if (rem < 48) {
                int g = rem >> 4, q = rem & 15;
                if (((grow & (L_DIM - 1)) + t0) >= 0) {
                    CP_ASYNC16(sb + SG_OFF + r * 816 + g * 256 + q * 16,
                               &g_G[(size_t)(grow + t0) * G3 + g * H_DIM + n0 + q * 4]);
                }
            } else {
                int q = rem - 48;
                CP_ASYNC16(sb + SH_OFF + r * 272 + q * 16,
                           &Hi[(size_t)grow * H_DIM + n0 + q * 4]);
            }
        }
        CP_COMMIT();
        CP_WAIT(0);
        __syncthreads();

        // --- GRU compute from smem, results staged to SO/SOh ---
#pragma unroll
        for (int mt = 0; mt < 2; mt++)
#pragma unroll
            for (int rp = 0; rp < 2; rp++) {
                int rloc = warp_m * 32 + mt * 16 + rp * 8 + rl;
                int grow = gm + rloc;
                bool valid = ((grow & (L_DIM - 1)) + t0) >= 0;
#pragma unroll
                for (int nt = 0; nt < 2; nt++) {
                    int cloc = colb + nt * 8 + cl;
                    float2 gr, gz, gn;
                    if (valid) {
                        const char* gp = smc + SG_OFF + rloc * 816 + cloc * 4;
                        gr = *(const float2*)(gp);
                        gz = *(const float2*)(gp + 256);
                        gn = *(const float2*)(gp + 512);
                    } else {
                        gr = *(const float2*)&bih[n0 + cloc];
                        gz = *(const float2*)&bih[H_DIM + n0 + cloc];
                        gn = *(const float2*)&bih[2 * H_DIM + n0 + cloc];
                    }
                    float2 br = *(const float2*)&bhh[n0 + cloc];
                    float2 bz = *(const float2*)&bhh[H_DIM + n0 + cloc];
                    float2 bn = *(const float2*)&bhh[2 * H_DIM + n0 + cloc];
                    float2 h  = *(const float2*)(smc + SH_OFF + rloc * 272 + cloc * 4);
                    float2 o;
                    {
                        float r  = sigm(gr.x + acc[0][mt][nt][rp * 2] + br.x);
                        float z  = sigm(gz.x + acc[1][mt][nt][rp * 2] + bz.x);
                        float nn = tanh_apx(gn.x + r * (acc[2][mt][nt][rp * 2] + bn.x));
                        o.x = (1.0f - z) * nn + z * h.x;
                    }
                    {
                        float r  = sigm(gr.y + acc[0][mt][nt][rp * 2 + 1] + br.y);
                        float z  = sigm(gz.y + acc[1][mt][nt][rp * 2 + 1] + bz.y);
                        float nn = tanh_apx(gn.y + r * (acc[2][mt][nt][rp * 2 + 1] + bn.y));
                        o.y = (1.0f - z) * nn + z * h.y;
                    }
                    *(float2*)(smc + SO_OFF + rloc * 272 + cloc * 4) = o;
                    if (!last)
                        *(__half2*)(smc + SOH_OFF + rloc * 144 + cloc * 2) =
                            __float22half2_rn(o);
                }
            }
        __syncthreads();

        // --- coalesced store-out ---
        for (int j = tid; j < 1024; j += THREADS) {      // f32: 16 float4/row
            int r = j >> 4, c = (j & 15) << 2;
            float4 v = *(const float4*)(smc + SO_OFF + r * 272 + c * 4);
            *(float4*)&Ho[(size_t)(gm + r) * H_DIM + n0 + c] = v;
        }
        if (!last) {
            for (int j = tid; j < 512; j += THREADS) {   // fp16: 8 uint4/row
                int r = j >> 3, c = (j & 7) << 3;
                uint4 v = *(const uint4*)(smc + SOH_OFF + r * 144 + c * 2);
                *(uint4*)&Hoh[(size_t)(gm + r) * H_DIM + n0 + c] = v;
            }
        }
    }
}

// ---------------------------------------------------------------------------
// Window step t=0 (h=0, pure elementwise)
// ---------------------------------------------------------------------------
__global__ __launch_bounds__(256) void step0_kernel(
    const float* __restrict__ bih, const float* __restrict__ bhh)
{
    const int row = blockIdx.x;
    const int col = threadIdx.x;
    const int l = row & (L_DIM - 1);
    const int src = l - (KWIN - 1);

    float gir, giz, gin;
    if (src >= 0) {
        const float* Gp = &g_G[(size_t)(row - l + src) * G3 + col];
        gir = Gp[0]; giz = Gp[H_DIM]; gin = Gp[2 * H_DIM];
    } else {
        gir = bih[col]; giz = bih[col + H_DIM]; gin = bih[col + 2 * H_DIM];
    }
    float r  = sigm(gir + bhh[col]);
    float z  = sigm(giz + bhh[col + H_DIM]);
    float nn = tanh_apx(gin + r * bhh[col + 2 * H_DIM]);
    float h0 = (1.0f - z) * nn;
    g_H[0][(size_t)row * H_DIM + col] = h0;
    g_Hh[0][(size_t)row * H_DIM + col] = __float2half(h0);
}

// ---------------------------------------------------------------------------
// Launch: prep -> proj -> step0 -> 15 x fused mma step (last writes d_out)
// ---------------------------------------------------------------------------
extern "C" void kernel_launch(void* const* d_in, const int* in_sizes, int n_in,
                              void* d_out, int out_size)
{
    const float* x   = (const float*)d_in[0];
    const float* Wih = (const float*)d_in[1];
    const float* Whh = (const float*)d_in[2];
    const float* bih = (const float*)d_in[3];
    const float* bhh = (const float*)d_in[4];
    float* out = (float*)d_out;

    cudaFuncSetAttribute(gemm3_kernel, cudaFuncAttributeMaxDynamicSharedMemorySize, SMEM_BYTES);

    prep_kernel<<<(R_TOTAL * KDIM + 255) / 256, 256>>>(x, Wih, Whh);
    dim3 grid(R_TOTAL / TILE_M, H_DIM / 64);   // (256, 4)
    gemm3_kernel<<<grid, THREADS, SMEM_BYTES>>>(bih, bhh, 0, 0, nullptr);
    step0_kernel<<<R_TOTAL, 256>>>(bih, bhh);
    for (int t = 1; t < KWIN; t++) {
        int in_idx = (t - 1) & 1;
        float* fin = (t == KWIN - 1) ? out : nullptr;
        gemm3_kernel<<<grid, THREADS, SMEM_BYTES>>>(bih, bhh, t, in_idx, fin);
    }
}

// round 11
// speedup vs baseline: 2.1891x; 1.2155x over previous
#include <cuda_runtime.h>
#include <cuda_fp16.h>
#include <cstdint>

// Problem dims (fixed)
#define L_DIM   1024
#define H_DIM   256
#define KWIN    16
#define R_TOTAL 16384
#define G3      768
#define KDIM    256

#define THREADS 256

// ---------------- persistent rnn kernel smem layout (bytes) ----------------
// HH: fp16 H double buffer, [64 rows][256 halves] per buf, 512B/row, XOR-swizzled
#define HH_OFF   0
#define HH_BUF   32768
// SB: W_hh k-chunk ring, [192 rows][64 halves] per buf, 128B/row, XOR-swizzled.
// After the mainloop the 2 bufs (49152B contiguous) are reused as the G stage:
// [64 rows][192 f32] = 768B/row, XOR-swizzled.
#define SB_OFF   65536
#define SB_BUF   24576
#define RNN_SMEM 114688     // 112KB -> 2 CTAs/SM

// ---------------- proj kernel (R9 layout) ----------------
#define TILE_M  64
#define NTOT    192
#define BK      64
#define NCHUNK  (KDIM / BK)
#define AS      72
#define BS      72
#define ABUF    (TILE_M * AS)
#define BBUF    (NTOT * BS)
#define BUFF    (ABUF + BBUF)
#define PROJ_SMEM (3 * BUFF * 2)    // 110592
#define SG_OFF  0                   // proj G staging: 64 rows x 816B

// Scratch (allocation-free rule: device globals)
__device__ float  g_G[R_TOTAL * G3];        // input projections incl. b_ih (f32)
__device__ float  g_Hf[R_TOTAL * H_DIM];    // f32 hidden state carry (in-place)
__device__ __half g_Xh[R_TOTAL * KDIM];     // fp16 x
__device__ __half g_Wih_h[G3 * KDIM];       // fp16 W_ih
__device__ __half g_Whh_h[G3 * KDIM];       // fp16 W_hh

// ---------------------------------------------------------------------------
// helpers
// ---------------------------------------------------------------------------
__device__ __forceinline__ uint32_t smem_u32(const void* p) {
    uint32_t a;
    asm("{ .reg .u64 t; cvta.to.shared.u64 t, %1; cvt.u32.u64 %0, t; }" : "=r"(a) : "l"(p));
    return a;
}
__device__ __forceinline__ float tanh_apx(float x) {
    float y; asm("tanh.approx.f32 %0, %1;" : "=f"(y) : "f"(x)); return y;
}
__device__ __forceinline__ float sigm(float x) {
    return fmaf(tanh_apx(0.5f * x), 0.5f, 0.5f);
}

#define CP_ASYNC16(dst, src) \
    asm volatile("cp.async.cg.shared.global [%0], [%1], 16;" :: "r"(dst), "l"(src) : "memory")
#define CP_COMMIT() asm volatile("cp.async.commit_group;" ::: "memory")
#define CP_WAIT(n)  asm volatile("cp.async.wait_group %0;" :: "n"(n) : "memory")

#define LDSM_X4(r0, r1, r2, r3, addr)                                        \
    asm volatile("ldmatrix.sync.aligned.m8n8.x4.shared.b16 {%0,%1,%2,%3}, [%4];" \
        : "=r"(r0), "=r"(r1), "=r"(r2), "=r"(r3) : "r"(addr))

__device__ __forceinline__ void mma_f16(float* d, const uint32_t* a, uint32_t b0, uint32_t b1) {
    asm volatile(
        "mma.sync.aligned.m16n8k16.row.col.f32.f16.f16.f32 "
        "{%0,%1,%2,%3}, {%4,%5,%6,%7}, {%8,%9}, {%0,%1,%2,%3};"
        : "+f"(d[0]), "+f"(d[1]), "+f"(d[2]), "+f"(d[3])
        : "r"(a[0]), "r"(a[1]), "r"(a[2]), "r"(a[3]), "r"(b0), "r"(b1));
}

// ---------------------------------------------------------------------------
// prep: convert x, W_ih, W_hh to fp16 (RN)
// ---------------------------------------------------------------------------
__global__ __launch_bounds__(256) void prep_kernel(
    const float* __restrict__ x,
    const float* __restrict__ Wih,
    const float* __restrict__ Whh)
{
    int i = blockIdx.x * 256 + threadIdx.x;
    if (i < R_TOTAL * KDIM) g_Xh[i] = __float2half(x[i]);
    if (i < G3 * KDIM) {
        g_Wih_h[i] = __float2half(Wih[i]);
        g_Whh_h[i] = __float2half(Whh[i]);
    }
}

// ---------------------------------------------------------------------------
// proj kernel (R9 structure, mode-0 only): G = x @ W_ih^T + b_ih
// ---------------------------------------------------------------------------
__global__ __launch_bounds__(THREADS, 2) void proj_kernel(const float* __restrict__ bih)
{
    extern __shared__ __half smf[];
    char* const smc = (char*)smf;
    const uint32_t sb = smem_u32(smf);
    const int tid = threadIdx.x;
    const int lane = tid & 31, wid = tid >> 5;
    const int warp_m = wid & 1, wn = wid >> 1;
    const int gm = blockIdx.x * TILE_M;
    const int n0 = blockIdx.y * 64;

    float acc[3][2][2][4];
#pragma unroll
    for (int g = 0; g < 3; g++)
#pragma unroll
        for (int mt = 0; mt < 2; mt++)
#pragma unroll
            for (int nt = 0; nt < 2; nt++)
#pragma unroll
                for (int e = 0; e < 4; e++) acc[g][mt][nt][e] = 0.0f;

    auto issue = [&](int k0, int buf) {
        const uint32_t abase = sb + buf * (BUFF * 2);
#pragma unroll
        for (int i = 0; i < 2; i++) {
            int j = tid + i * THREADS;
            int row = j >> 3, kv = (j & 7) << 3;
            CP_ASYNC16(abase + (row * AS + kv) * 2,
                       &g_Xh[(size_t)(gm + row) * KDIM + k0 + kv]);
        }
        const uint32_t bbase = abase + ABUF * 2;
#pragma unroll
        for (int i = 0; i < 6; i++) {
            int j = tid + i * THREADS;
            int row = j >> 3, kv = (j & 7) << 3;
            int g = row >> 6, nl = row & 63;
            CP_ASYNC16(bbase + (row * BS + kv) * 2,
                       &g_Wih_h[(size_t)(g * H_DIM + n0 + nl) * KDIM + k0 + kv]);
        }
        CP_COMMIT();
    };

    const int lr8  = lane & 7;
    const int lbit = (lane >> 3) & 1;
    const int lhi  = lane >> 4;

    issue(0, 0);
    issue(BK, 1);
#pragma unroll 1
    for (int c = 0; c < NCHUNK; c++) {
        if (c == NCHUNK - 1) { CP_WAIT(0); } else { CP_WAIT(1); }
        __syncthreads();
        if (c + 2 < NCHUNK) issue((c + 2) * BK, (c + 2) % 3);

        const uint32_t sA = sb + (c % 3) * (BUFF * 2);
        const uint32_t sB = sA + ABUF * 2;
#pragma unroll
        for (int ks = 0; ks < 4; ks++) {
            const int kk = ks * 16;
            uint32_t a[2][4];
#pragma unroll
            for (int mt = 0; mt < 2; mt++) {
                int row = warp_m * 32 + mt * 16 + lr8 + 8 * lbit;
                int col = kk + 8 * lhi;
                LDSM_X4(a[mt][0], a[mt][1], a[mt][2], a[mt][3],
                        sA + (row * AS + col) * 2);
            }
#pragma unroll
            for (int g = 0; g < 3; g++) {
                uint32_t b[4];
                int row = g * 64 + wn * 16 + lr8 + 8 * lhi;
                int col = kk + 8 * lbit;
                LDSM_X4(b[0], b[1], b[2], b[3], sB + (row * BS + col) * 2);
#pragma unroll
                for (int mt = 0; mt < 2; mt++) {
                    mma_f16(acc[g][mt][0], a[mt], b[0], b[1]);
                    mma_f16(acc[g][mt][1], a[mt], b[2], b[3]);
                }
            }
        }
    }
    __syncthreads();

    const int rl = lane >> 2, cl = (lane & 3) * 2;
    const int colb = wn * 16;
#pragma unroll
    for (int mt = 0; mt < 2; mt++)
#pragma unroll
        for (int rp = 0; rp < 2; rp++) {
            int rloc = warp_m * 32 + mt * 16 + rp * 8 + rl;
#pragma unroll
            for (int g = 0; g < 3; g++)
#pragma unroll
                for (int nt = 0; nt < 2; nt++) {
                    int cloc = colb + nt * 8 + cl;
                    float2 bv = *(const float2*)&bih[g * H_DIM + n0 + cloc];
                    float2 o;
                    o.x = acc[g][mt][nt][rp * 2 + 0] + bv.x;
                    o.y = acc[g][mt][nt][rp * 2 + 1] + bv.y;
                    *(float2*)(smc + SG_OFF + rloc * 816 + (g * 64 + cloc) * 4) = o;
                }
        }
    __syncthreads();
    for (int j = tid; j < 64 * 48; j += THREADS) {
        int r = j / 48, c2 = j % 48;
        int g = c2 >> 4, q = c2 & 15;
        float4 v = *(const float4*)(smc + SG_OFF + r * 816 + c2 * 16);
        *(float4*)&g_G[(size_t)(gm + r) * G3 + g * H_DIM + n0 + q * 4] = v;
    }
}

// ---------------------------------------------------------------------------
// Persistent RNN kernel: one CTA owns 64 rows x ALL 768 gate cols, runs the
// full 16-step recurrence with H (fp16) resident in smem.
// ---------------------------------------------------------------------------
__global__ __launch_bounds__(THREADS, 2) void rnn_kernel(
    const float* __restrict__ bih,
    const float* __restrict__ bhh,
    float* __restrict__ fin)
{
    extern __shared__ char smc[];
    const uint32_t sb = smem_u32(smc);
    const int tid = threadIdx.x;
    const int lane = tid & 31, wid = tid >> 5;
    const int warp_m = wid & 1, wn = wid >> 1;
    const int gm = blockIdx.x * 64;
    const int gmL = gm & (L_DIM - 1);

    const int lr8  = lane & 7;
    const int lbit = (lane >> 3) & 1;
    const int lhi  = lane >> 4;
    const int rl = lane >> 2, cl = (lane & 3) * 2;
    const int colb = wn * 16;

    // ---- t = 0: h0 from G (h starts at zero), write to HH0 + g_Hf ----
    for (int j = tid; j < 64 * 128; j += THREADS) {
        int r = j >> 7;
        int cp = (j & 127) * 2;          // even col
        int grow = gm + r;
        bool valid = (gmL + r - (KWIN - 1)) >= 0;
        float2 gir, giz, gin;
        if (valid) {
            const float* Gp = &g_G[(size_t)(grow - (KWIN - 1)) * G3];
            gir = *(const float2*)&Gp[cp];
            giz = *(const float2*)&Gp[H_DIM + cp];
            gin = *(const float2*)&Gp[2 * H_DIM + cp];
        } else {
            gir = *(const float2*)&bih[cp];
            giz = *(const float2*)&bih[H_DIM + cp];
            gin = *(const float2*)&bih[2 * H_DIM + cp];
        }
        float2 br = *(const float2*)&bhh[cp];
        float2 bz = *(const float2*)&bhh[H_DIM + cp];
        float2 bn = *(const float2*)&bhh[2 * H_DIM + cp];
        float2 o;
        {
            float rr = sigm(gir.x + br.x);
            float zz = sigm(giz.x + bz.x);
            float nn = tanh_apx(gin.x + rr * bn.x);
            o.x = (1.0f - zz) * nn;
        }
        {
            float rr = sigm(gir.y + br.y);
            float zz = sigm(giz.y + bz.y);
            float nn = tanh_apx(gin.y + rr * bn.y);
            o.y = (1.0f - zz) * nn;
        }
        *(__half2*)(smc + HH_OFF + r * 512 + ((cp * 2) ^ ((r & 7) << 4))) =
            __float22half2_rn(o);
        *(float2*)&g_Hf[(size_t)grow * H_DIM + cp] = o;
    }
    __syncthreads();

    // ---- steps t = 1..15 ----
#pragma unroll 1
    for (int t = 1; t < KWIN; t++) {
        const int cur = (t - 1) & 1;
        const int nxt = t & 1;
        const int t0 = t - (KWIN - 1);
        const bool last = (t == KWIN - 1);
        const uint32_t sA = sb + HH_OFF + cur * HH_BUF;

#pragma unroll 1
        for (int nc = 0; nc < 4; nc++) {
            const int n0 = nc * 64;

            float acc[3][2][2][4];
#pragma unroll
            for (int g = 0; g < 3; g++)
#pragma unroll
                for (int mt = 0; mt < 2; mt++)
#pragma unroll
                    for (int nt = 0; nt < 2; nt++)
#pragma unroll
                        for (int e = 0; e < 4; e++) acc[g][mt][nt][e] = 0.0f;

            auto issueB = [&](int kc, int buf) {
                const uint32_t bbase = sb + SB_OFF + buf * SB_BUF;
#pragma unroll
                for (int i = 0; i < 6; i++) {
                    int j = tid + i * THREADS;
                    int row = j >> 3, q = j & 7;     // row 0..191
                    int g = row >> 6, nl = row & 63;
                    CP_ASYNC16(bbase + row * 128 + ((q * 16) ^ ((row & 7) << 4)),
                               &g_Whh_h[(size_t)(g * H_DIM + n0 + nl) * KDIM + kc * 64 + q * 8]);
                }
                CP_COMMIT();
            };

            issueB(0, 0);
#pragma unroll 1
            for (int kc = 0; kc < 4; kc++) {
                CP_WAIT(0);
                __syncthreads();
                if (kc < 3) issueB(kc + 1, (kc + 1) & 1);
                const uint32_t sBb = sb + SB_OFF + (kc & 1) * SB_BUF;
#pragma unroll
                for (int ks = 0; ks < 4; ks++) {
                    uint32_t a[2][4];
#pragma unroll
                    for (int mt = 0; mt < 2; mt++) {
                        int row = warp_m * 32 + mt * 16 + lr8 + 8 * lbit;
                        int kbyte = kc * 128 + ks * 32 + lhi * 16;
                        LDSM_X4(a[mt][0], a[mt][1], a[mt][2], a[mt][3],
                                sA + row * 512 + (kbyte ^ ((row & 7) << 4)));
                    }
#pragma unroll
                    for (int g = 0; g < 3; g++) {
                        uint32_t b[4];
                        int row = g * 64 + wn * 16 + lr8 + 8 * lhi;
                        int kbyte = ks * 32 + lbit * 16;
                        LDSM_X4(b[0], b[1], b[2], b[3],
                                sBb + row * 128 + (kbyte ^ ((row & 7) << 4)));
#pragma unroll
                        for (int mt = 0; mt < 2; mt++) {
                            mma_f16(acc[g][mt][0], a[mt], b[0], b[1]);
                            mma_f16(acc[g][mt][1], a[mt], b[2], b[3]);
                        }
                    }
                }
            }
            __syncthreads();   // B ring drained -> reuse as G stage

            // stage G window [64 rows x 192 f32] into SB region (swizzled)
#pragma unroll
            for (int i = 0; i < 12; i++) {
                int j = tid + i * THREADS;           // 0..3071
                int r = j / 48, c2 = j % 48;
                int gg = c2 >> 4, q = c2 & 15;
                if (gmL + r + t0 >= 0)
                    CP_ASYNC16(sb + SB_OFF + r * 768 + ((gg * 256 + q * 16) ^ ((r & 7) << 4)),
                               &g_G[(size_t)(gm + r + t0) * G3 + gg * H_DIM + n0 + q * 4]);
            }
            CP_COMMIT();
            CP_WAIT(0);
            __syncthreads();

            // GRU epilogue (fragment-mapped, G from staged smem)
#pragma unroll
            for (int mt = 0; mt < 2; mt++)
#pragma unroll
                for (int rp = 0; rp < 2; rp++) {
                    int rloc = warp_m * 32 + mt * 16 + rp * 8 + rl;
                    int grow = gm + rloc;
                    bool valid = (gmL + rloc + t0) >= 0;
                    int sw = (rloc & 7) << 4;
#pragma unroll
                    for (int nt = 0; nt < 2; nt++) {
                        int cloc = colb + nt * 8 + cl;
                        int col = n0 + cloc;
                        float2 gr, gz, gn;
                        if (valid) {
                            const char* gp = smc + SB_OFF + rloc * 768;
                            gr = *(const float2*)(gp + ((cloc * 4) ^ sw));
                            gz = *(const float2*)(gp + ((256 + cloc * 4) ^ sw));
                            gn = *(const float2*)(gp + ((512 + cloc * 4) ^ sw));
                        } else {
                            gr = *(const float2*)&bih[col];
                            gz = *(const float2*)&bih[H_DIM + col];
                            gn = *(const float2*)&bih[2 * H_DIM + col];
                        }
                        float2 br = *(const float2*)&bhh[col];
                        float2 bz = *(const float2*)&bhh[H_DIM + col];
                        float2 bn = *(const float2*)&bhh[2 * H_DIM + col];
                        float2 h = *(const float2*)&g_Hf[(size_t)grow * H_DIM + col];
                        float2 o;
                        {
                            float r  = sigm(gr.x + acc[0][mt][nt][rp * 2] + br.x);
                            float z  = sigm(gz.x + acc[1][mt][nt][rp * 2] + bz.x);
                            float nn = tanh_apx(gn.x + r * (acc[2][mt][nt][rp * 2] + bn.x));
                            o.x = (1.0f - z) * nn + z * h.x;
                        }
                        {
                            float r  = sigm(gr.y + acc[0][mt][nt][rp * 2 + 1] + br.y);
                            float z  = sigm(gz.y + acc[1][mt][nt][rp * 2 + 1] + bz.y);
                            float nn = tanh_apx(gn.y + r * (acc[2][mt][nt][rp * 2 + 1] + bn.y));
                            o.y = (1.0f - z) * nn + z * h.y;
                        }
                        if (last) {
                            *(float2*)&fin[(size_t)grow * H_DIM + col] = o;
                        } else {
                            *(__half2*)(smc + HH_OFF + nxt * HH_BUF + rloc * 512 +
                                        ((col * 2) ^ sw)) = __float22half2_rn(o);
                            *(float2*)&g_Hf[(size_t)grow * H_DIM + col] = o;
                        }
                    }
                }
            __syncthreads();   // staged-G region freed before next nc's B loads
        }
    }
}

// ---------------------------------------------------------------------------
// Launch: prep -> proj -> persistent rnn (3 launches total)
// ---------------------------------------------------------------------------
extern "C" void kernel_launch(void* const* d_in, const int* in_sizes, int n_in,
                              void* d_out, int out_size)
{
    const float* x   = (const float*)d_in[0];
    const float* Wih = (const float*)d_in[1];
    const float* Whh = (const float*)d_in[2];
    const float* bih = (const float*)d_in[3];
    const float* bhh = (const float*)d_in[4];
    float* out = (float*)d_out;

    cudaFuncSetAttribute(proj_kernel, cudaFuncAttributeMaxDynamicSharedMemorySize, PROJ_SMEM);
    cudaFuncSetAttribute(rnn_kernel,  cudaFuncAttributeMaxDynamicSharedMemorySize, RNN_SMEM);

    prep_kernel<<<(R_TOTAL * KDIM + 255) / 256, 256>>>(x, Wih, Whh);
    dim3 pgrid(R_TOTAL / TILE_M, H_DIM / 64);   // (256, 4)
    proj_kernel<<<pgrid, THREADS, PROJ_SMEM>>>(bih);
    rnn_kernel<<<R_TOTAL / 64, THREADS, RNN_SMEM>>>(bih, bhh, out);
}

// round 13
// speedup vs baseline: 2.4177x; 1.1044x over previous
#include <cuda_runtime.h>
#include <cuda_fp16.h>
#include <cstdint>

// Problem dims (fixed)
#define L_DIM   1024
#define H_DIM   256
#define KWIN    16
#define R_TOTAL 16384
#define G3      768
#define KDIM    256

#define THREADS 256

// ---------------- persistent rnn kernel smem layout (bytes) ----------------
// HH: fp16 H double buffer, [64 rows][256 halves] per buf, 512B/row, XOR-swizzled
#define HH_OFF   0
#define HH_BUF   32768
// SB: W_hh k-chunk ring, [192 rows][64 halves] per buf, 128B/row, XOR-swizzled.
// After the mainloop: buf0 (24KB) reused as fp16 G stage (64 rows x 384B),
// buf1 (first 16KB) as f32 H stage / out stage (64 rows x 256B).
#define SB_OFF   65536
#define SB_BUF   24576
#define SH_STG   (SB_OFF + SB_BUF)
#define RNN_SMEM 114688     // 112KB -> 2 CTAs/SM

// ---------------- proj kernel ----------------
#define TILE_M  64
#define NTOT    192
#define BK      64
#define NCHUNK  (KDIM / BK)
#define AS      72
#define BS      72
#define ABUF    (TILE_M * AS)
#define BBUF    (NTOT * BS)
#define BUFF    (ABUF + BBUF)
#define PROJ_SMEM (3 * BUFF * 2)    // 110592
#define SG_OFF  0                   // proj G staging: 64 rows x 384B, XOR-swizzled

// Scratch (allocation-free rule: device globals)
__device__ __half g_Gh[R_TOTAL * G3];       // input projections incl. b_ih (fp16)
__device__ float  g_Hf[R_TOTAL * H_DIM];    // f32 hidden state carry (in-place)
__device__ __half g_Xh[R_TOTAL * KDIM];     // fp16 x
__device__ __half g_Wih_h[G3 * KDIM];       // fp16 W_ih
__device__ __half g_Whh_h[G3 * KDIM];       // fp16 W_hh

// ---------------------------------------------------------------------------
// helpers
// ---------------------------------------------------------------------------
__device__ __forceinline__ uint32_t smem_u32(const void* p) {
    uint32_t a;
    asm("{ .reg .u64 t; cvta.to.shared.u64 t, %1; cvt.u32.u64 %0, t; }" : "=r"(a) : "l"(p));
    return a;
}
__device__ __forceinline__ float tanh_apx(float x) {
    float y; asm("tanh.approx.f32 %0, %1;" : "=f"(y) : "f"(x)); return y;
}
__device__ __forceinline__ float sigm(float x) {
    return fmaf(tanh_apx(0.5f * x), 0.5f, 0.5f);
}
__device__ __forceinline__ uint32_t h2_bits(__half2 h) {
    uint32_t u; __builtin_memcpy(&u, &h, 4); return u;
}

#define CP_ASYNC16(dst, src) \
    asm volatile("cp.async.cg.shared.global [%0], [%1], 16;" :: "r"(dst), "l"(src) : "memory")
#define CP_COMMIT() asm volatile("cp.async.commit_group;" ::: "memory")
#define CP_WAIT(n)  asm volatile("cp.async.wait_group %0;" :: "n"(n) : "memory")

#define LDSM_X4(r0, r1, r2, r3, addr)                                        \
    asm volatile("ldmatrix.sync.aligned.m8n8.x4.shared.b16 {%0,%1,%2,%3}, [%4];" \
        : "=r"(r0), "=r"(r1), "=r"(r2), "=r"(r3) : "r"(addr))

__device__ __forceinline__ void mma_f16(float* d, const uint32_t* a, uint32_t b0, uint32_t b1) {
    asm volatile(
        "mma.sync.aligned.m16n8k16.row.col.f32.f16.f16.f32 "
        "{%0,%1,%2,%3}, {%4,%5,%6,%7}, {%8,%9}, {%0,%1,%2,%3};"
        : "+f"(d[0]), "+f"(d[1]), "+f"(d[2]), "+f"(d[3])
        : "r"(a[0]), "r"(a[1]), "r"(a[2]), "r"(a[3]), "r"(b0), "r"(b1));
}

// ---------------------------------------------------------------------------
// prep: convert x, W_ih, W_hh to fp16 (RN), float4-vectorized
// ---------------------------------------------------------------------------
__global__ __launch_bounds__(256) void prep_kernel(
    const float* __restrict__ x,
    const float* __restrict__ Wih,
    const float* __restrict__ Whh)
{
    int i = (blockIdx.x * 256 + threadIdx.x) * 4;
    if (i < R_TOTAL * KDIM) {
        float4 v = *(const float4*)&x[i];
        uint2 o;
        o.x = h2_bits(__floats2half2_rn(v.x, v.y));
        o.y = h2_bits(__floats2half2_rn(v.z, v.w));
        *(uint2*)&g_Xh[i] = o;
    }
    if (i < G3 * KDIM) {
        float4 v = *(const float4*)&Wih[i];
        uint2 o;
        o.x = h2_bits(__floats2half2_rn(v.x, v.y));
        o.y = h2_bits(__floats2half2_rn(v.z, v.w));
        *(uint2*)&g_Wih_h[i] = o;
        float4 w = *(const float4*)&Whh[i];
        o.x = h2_bits(__floats2half2_rn(w.x, w.y));
        o.y = h2_bits(__floats2half2_rn(w.z, w.w));
        *(uint2*)&g_Whh_h[i] = o;
    }
}

// ---------------------------------------------------------------------------
// proj kernel: G = x @ W_ih^T + b_ih  -> g_Gh (fp16), staged coalesced store
// ---------------------------------------------------------------------------
__global__ __launch_bounds__(THREADS, 2) void proj_kernel(const float* __restrict__ bih)
{
    extern __shared__ __half smf[];
    char* const smc = (char*)smf;
    const uint32_t sb = smem_u32(smf);
    const int tid = threadIdx.x;
    const int lane = tid & 31, wid = tid >> 5;
    const int warp_m = wid & 1, wn = wid >> 1;
    const int gm = blockIdx.x * TILE_M;
    const int n0 = blockIdx.y * 64;

    float acc[3][2][2][4];
#pragma unroll
    for (int g = 0; g < 3; g++)
#pragma unroll
        for (int mt = 0; mt < 2; mt++)
#pragma unroll
            for (int nt = 0; nt < 2; nt++)
#pragma unroll
                for (int e = 0; e < 4; e++) acc[g][mt][nt][e] = 0.0f;

    auto issue = [&](int k0, int buf) {
        const uint32_t abase = sb + buf * (BUFF * 2);
#pragma unroll
        for (int i = 0; i < 2; i++) {
            int j = tid + i * THREADS;
            int row = j >> 3, kv = (j & 7) << 3;
            CP_ASYNC16(abase + (row * AS + kv) * 2,
                       &g_Xh[(size_t)(gm + row) * KDIM + k0 + kv]);
        }
        const uint32_t bbase = abase + ABUF * 2;
#pragma unroll
        for (int i = 0; i < 6; i++) {
            int j = tid + i * THREADS;
            int row = j >> 3, kv = (j & 7) << 3;
            int g = row >> 6, nl = row & 63;
            CP_ASYNC16(bbase + (row * BS + kv) * 2,
                       &g_Wih_h[(size_t)(g * H_DIM + n0 + nl) * KDIM + k0 + kv]);
        }
        CP_COMMIT();
    };

    const int lr8  = lane & 7;
    const int lbit = (lane >> 3) & 1;
    const int lhi  = lane >> 4;

    issue(0, 0);
    issue(BK, 1);
#pragma unroll 1
    for (int c = 0; c < NCHUNK; c++) {
        if (c == NCHUNK - 1) { CP_WAIT(0); } else { CP_WAIT(1); }
        __syncthreads();
        if (c + 2 < NCHUNK) issue((c + 2) * BK, (c + 2) % 3);

        const uint32_t sA = sb + (c % 3) * (BUFF * 2);
        const uint32_t sB = sA + ABUF * 2;
#pragma unroll
        for (int ks = 0; ks < 4; ks++) {
            const int kk = ks * 16;
            uint32_t a[2][4];
#pragma unroll
            for (int mt = 0; mt < 2; mt++) {
                int row = warp_m * 32 + mt * 16 + lr8 + 8 * lbit;
                int col = kk + 8 * lhi;
                LDSM_X4(a[mt][0], a[mt][1], a[mt][2], a[mt][3],
                        sA + (row * AS + col) * 2);
            }
#pragma unroll
            for (int g = 0; g < 3; g++) {
                uint32_t b[4];
                int row = g * 64 + wn * 16 + lr8 + 8 * lhi;
                int col = kk + 8 * lbit;
                LDSM_X4(b[0], b[1], b[2], b[3], sB + (row * BS + col) * 2);
#pragma unroll
                for (int mt = 0; mt < 2; mt++) {
                    mma_f16(acc[g][mt][0], a[mt], b[0], b[1]);
                    mma_f16(acc[g][mt][1], a[mt], b[2], b[3]);
                }
            }
        }
    }
    __syncthreads();

    const int rl = lane >> 2, cl = (lane & 3) * 2;
    const int colb = wn * 16;
#pragma unroll
    for (int mt = 0; mt < 2; mt++)
#pragma unroll
        for (int rp = 0; rp < 2; rp++) {
            int rloc = warp_m * 32 + mt * 16 + rp * 8 + rl;
            int sw = (rloc & 7) << 4;
#pragma unroll
            for (int g = 0; g < 3; g++)
#pragma unroll
                for (int nt = 0; nt < 2; nt++) {
                    int cloc = colb + nt * 8 + cl;
                    float2 bv = *(const float2*)&bih[g * H_DIM + n0 + cloc];
                    int b = (g * 64 + cloc) * 2;
                    *(__half2*)(smc + SG_OFF + rloc * 384 + ((b & ~15) ^ sw) + (b & 15)) =
                        __floats2half2_rn(acc[g][mt][nt][rp * 2 + 0] + bv.x,
                                          acc[g][mt][nt][rp * 2 + 1] + bv.y);
                }
        }
    __syncthreads();
    for (int j = tid; j < 64 * 24; j += THREADS) {
        int r = j / 24, c = j % 24;
        int g = c >> 3, q = c & 7;
        uint4 v = *(const uint4*)(smc + SG_OFF + r * 384 + ((c * 16) ^ ((r & 7) << 4)));
        *(uint4*)&g_Gh[(size_t)(gm + r) * G3 + g * H_DIM + n0 + q * 8] = v;
    }
}

// ---------------------------------------------------------------------------
// Persistent RNN kernel: one CTA owns 64 rows x ALL 768 gate cols.
// ---------------------------------------------------------------------------
__global__ __launch_bounds__(THREADS, 2) void rnn_kernel(
    const float* __restrict__ bih,
    const float* __restrict__ bhh,
    float* __restrict__ fin)
{
    extern __shared__ char smc[];
    const uint32_t sb = smem_u32(smc);
    const int tid = threadIdx.x;
    const int lane = tid & 31, wid = tid >> 5;
    const int warp_m = wid & 1, wn = wid >> 1;
    const int gm = blockIdx.x * 64;
    const int gmL = gm & (L_DIM - 1);

    const int lr8  = lane & 7;
    const int lbit = (lane >> 3) & 1;
    const int lhi  = lane >> 4;
    const int rl = lane >> 2, cl = (lane & 3) * 2;
    const int colb = wn * 16;

    // ---- t = 0: h0 from G (h starts at zero), write to HH0 + g_Hf ----
    for (int j = tid; j < 64 * 128; j += THREADS) {
        int r = j >> 7;
        int cp = (j & 127) * 2;
        int grow = gm + r;
        bool valid = (gmL + r - (KWIN - 1)) >= 0;
        float2 gir, giz, gin;
        if (valid) {
            const __half* Gp = &g_Gh[(size_t)(grow - (KWIN - 1)) * G3];
            gir = __half22float2(*(const __half2*)&Gp[cp]);
            giz = __half22float2(*(const __half2*)&Gp[H_DIM + cp]);
            gin = __half22float2(*(const __half2*)&Gp[2 * H_DIM + cp]);
        } else {
            gir = *(const float2*)&bih[cp];
            giz = *(const float2*)&bih[H_DIM + cp];
            gin = *(const float2*)&bih[2 * H_DIM + cp];
        }
        float2 br = *(const float2*)&bhh[cp];
        float2 bz = *(const float2*)&bhh[H_DIM + cp];
        float2 bn = *(const float2*)&bhh[2 * H_DIM + cp];
        float2 o;
        {
            float rr = sigm(gir.x + br.x);
            float zz = sigm(giz.x + bz.x);
            float nn = tanh_apx(gin.x + rr * bn.x);
            o.x = (1.0f - zz) * nn;
        }
        {
            float rr = sigm(gir.y + br.y);
            float zz = sigm(giz.y + bz.y);
            float nn = tanh_apx(gin.y + rr * bn.y);
            o.y = (1.0f - zz) * nn;
        }
        *(__half2*)(smc + HH_OFF + r * 512 + ((cp * 2) ^ ((r & 7) << 4))) =
            __float22half2_rn(o);
        *(float2*)&g_Hf[(size_t)grow * H_DIM + cp] = o;
    }
    __syncthreads();

    // ---- steps t = 1..15 ----
#pragma unroll 1
    for (int t = 1; t < KWIN; t++) {
        const int cur = (t - 1) & 1;
        const int nxt = t & 1;
        const int t0 = t - (KWIN - 1);
        const bool last = (t == KWIN - 1);
        const uint32_t sA = sb + HH_OFF + cur * HH_BUF;

#pragma unroll 1
        for (int nc = 0; nc < 4; nc++) {
            const int n0 = nc * 64;

            float acc[3][2][2][4];
#pragma unroll
            for (int g = 0; g < 3; g++)
#pragma unroll
                for (int mt = 0; mt < 2; mt++)
#pragma unroll
                    for (int nt = 0; nt < 2; nt++)
#pragma unroll
                        for (int e = 0; e < 4; e++) acc[g][mt][nt][e] = 0.0f;

            auto issueB = [&](int kc, int buf) {
                const uint32_t bbase = sb + SB_OFF + buf * SB_BUF;
#pragma unroll
                for (int i = 0; i < 6; i++) {
                    int j = tid + i * THREADS;
                    int row = j >> 3, q = j & 7;
                    int g = row >> 6, nl = row & 63;
                    CP_ASYNC16(bbase + row * 128 + ((q * 16) ^ ((row & 7) << 4)),
                               &g_Whh_h[(size_t)(g * H_DIM + n0 + nl) * KDIM + kc * 64 + q * 8]);
                }
                CP_COMMIT();
            };
            // fp16 G stage into buf0 region (issued during kc=3 MMAs)
            auto issueG = [&]() {
#pragma unroll
                for (int i = 0; i < 6; i++) {
                    int j = tid + i * THREADS;           // 0..1535
                    int r = j / 24, c = j % 24;
                    int g = c >> 3, q = c & 7;
                    if (gmL + r + t0 >= 0)
                        CP_ASYNC16(sb + SB_OFF + r * 384 + ((c * 16) ^ ((r & 7) << 4)),
                                   &g_Gh[(size_t)(gm + r + t0) * G3 + g * H_DIM + n0 + q * 8]);
                }
                CP_COMMIT();
            };

            issueB(0, 0);
#pragma unroll 1
            for (int kc = 0; kc < 4; kc++) {
                CP_WAIT(0);
                __syncthreads();
                if (kc < 3) issueB(kc + 1, (kc + 1) & 1);
                else        issueG();
                const uint32_t sBb = sb + SB_OFF + (kc & 1) * SB_BUF;
#pragma unroll
                for (int ks = 0; ks < 4; ks++) {
                    uint32_t a[2][4];
#pragma unroll
                    for (int mt = 0; mt < 2; mt++) {
                        int row = warp_m * 32 + mt * 16 + lr8 + 8 * lbit;
                        int kbyte = kc * 128 + ks * 32 + lhi * 16;
                        LDSM_X4(a[mt][0], a[mt][1], a[mt][2], a[mt][3],
                                sA + row * 512 + (kbyte ^ ((row & 7) << 4)));
                    }
#pragma unroll
                    for (int g = 0; g < 3; g++) {
                        uint32_t b[4];
                        int row = g * 64 + wn * 16 + lr8 + 8 * lhi;
                        int kbyte = ks * 32 + lbit * 16;
                        LDSM_X4(b[0], b[1], b[2], b[3],
                                sBb + row * 128 + (kbyte ^ ((row & 7) << 4)));
#pragma unroll
                        for (int mt = 0; mt < 2; mt++) {
                            mma_f16(acc[g][mt][0], a[mt], b[0], b[1]);
                            mma_f16(acc[g][mt][1], a[mt], b[2], b[3]);
                        }
                    }
                }
            }
            __syncthreads();   // buf1 drained -> stage Hf there

            // f32 H stage (64 rows x 64 f32)
#pragma unroll
            for (int i = 0; i < 4; i++) {
                int j = tid + i * THREADS;               // 0..1023
                int r = j >> 4, q = j & 15;
                CP_ASYNC16(sb + SH_STG + r * 256 + ((q * 16) ^ ((r & 7) << 4)),
                           &g_Hf[(size_t)(gm + r) * H_DIM + n0 + q * 4]);
            }
            CP_COMMIT();
            CP_WAIT(0);
            __syncthreads();

            // GRU epilogue: G + h from smem stages; out written in place to H stage
#pragma unroll
            for (int mt = 0; mt < 2; mt++)
#pragma unroll
                for (int rp = 0; rp < 2; rp++) {
                    int rloc = warp_m * 32 + mt * 16 + rp * 8 + rl;
                    bool valid = (gmL + rloc + t0) >= 0;
                    int sw = (rloc & 7) << 4;
#pragma unroll
                    for (int nt = 0; nt < 2; nt++) {
                        int cloc = colb + nt * 8 + cl;
                        int col = n0 + cloc;
                        float2 gr, gz, gn;
                        if (valid) {
                            const char* gp = smc + SB_OFF + rloc * 384;
#pragma unroll
                            for (int g = 0; g < 3; g++) {
                                int b = (g * 64 + cloc) * 2;
                                float2 v = __half22float2(
                                    *(const __half2*)(gp + ((b & ~15) ^ sw) + (b & 15)));
                                if (g == 0) gr = v; else if (g == 1) gz = v; else gn = v;
                            }
                        } else {
                            gr = *(const float2*)&bih[col];
                            gz = *(const float2*)&bih[H_DIM + col];
                            gn = *(const float2*)&bih[2 * H_DIM + col];
                        }
                        float2 br = *(const float2*)&bhh[col];
                        float2 bz = *(const float2*)&bhh[H_DIM + col];
                        float2 bn = *(const float2*)&bhh[2 * H_DIM + col];
                        int hb = cloc * 4;
                        char* hp = smc + SH_STG + rloc * 256 + ((hb & ~15) ^ sw) + (hb & 15);
                        float2 h = *(const float2*)hp;
                        float2 o;
                        {
                            float r  = sigm(gr.x + acc[0][mt][nt][rp * 2] + br.x);
                            float z  = sigm(gz.x + acc[1][mt][nt][rp * 2] + bz.x);
                            float nn = tanh_apx(gn.x + r * (acc[2][mt][nt][rp * 2] + bn.x));
                            o.x = (1.0f - z) * nn + z * h.x;
                        }
                        {
                            float r  = sigm(gr.y + acc[0][mt][nt][rp * 2 + 1] + br.y);
                            float z  = sigm(gz.y + acc[1][mt][nt][rp * 2 + 1] + bz.y);
                            float nn = tanh_apx(gn.y + r * (acc[2][mt][nt][rp * 2 + 1] + bn.y));
                            o.y = (1.0f - z) * nn + z * h.y;
                        }
                        *(float2*)hp = o;                     // in-place out stage
                        if (!last)
                            *(__half2*)(smc + HH_OFF + nxt * HH_BUF + rloc * 512 +
                                        ((col * 2) ^ sw)) = __float22half2_rn(o);
                    }
                }
            __syncthreads();

            // coalesced store-out of h_new (or final output)
            float* __restrict__ Ho = last ? fin : g_Hf;
#pragma unroll
            for (int i = 0; i < 4; i++) {
                int j = tid + i * THREADS;
                int r = j >> 4, q = j & 15;
                float4 v = *(const float4*)(smc + SH_STG + r * 256 + ((q * 16) ^ ((r & 7) << 4)));
                *(float4*)&Ho[(size_t)(gm + r) * H_DIM + n0 + q * 4] = v;
            }
            __syncthreads();   // stage region freed before next nc's B loads
        }
    }
}

// ---------------------------------------------------------------------------
// Launch: prep -> proj -> persistent rnn (3 launches total)
// ---------------------------------------------------------------------------
extern "C" void kernel_launch(void* const* d_in, const int* in_sizes, int n_in,
                              void* d_out, int out_size)
{
    const float* x   = (const float*)d_in[0];
    const float* Wih = (const float*)d_in[1];
    const float* Whh = (const float*)d_in[2];
    const float* bih = (const float*)d_in[3];
    const float* bhh = (const float*)d_in[4];
    float* out = (float*)d_out;

    cudaFuncSetAttribute(proj_kernel, cudaFuncAttributeMaxDynamicSharedMemorySize, PROJ_SMEM);
    cudaFuncSetAttribute(rnn_kernel,  cudaFuncAttributeMaxDynamicSharedMemorySize, RNN_SMEM);

    prep_kernel<<<(R_TOTAL * KDIM / 4 + 255) / 256, 256>>>(x, Wih, Whh);
    dim3 pgrid(R_TOTAL / TILE_M, H_DIM / 64);   // (256, 4)
    proj_kernel<<<pgrid, THREADS, PROJ_SMEM>>>(bih);
    rnn_kernel<<<R_TOTAL / 64, THREADS, RNN_SMEM>>>(bih, bhh, out);
}

// round 14
// speedup vs baseline: 2.6558x; 1.0985x over previous
#include <cuda_runtime.h>
#include <cuda_fp16.h>
#include <cstdint>

// Problem dims (fixed)
#define L_DIM   1024
#define H_DIM   256
#define KWIN    16
#define R_TOTAL 16384
#define G3      768
#define KDIM    256

#define THREADS 256

// ---------------- persistent rnn kernel smem layout (bytes) ----------------
// HH: fp16 H double buffer, [64 rows][256 halves] per buf, 512B/row, XOR-swizzled
#define HH_OFF   0
#define HH_BUF   32768
// SB: W_hh k-chunk ring, [192 rows][64 halves] per buf, 128B/row, XOR-swizzled.
// After the mainloop: buf0 (24KB) reused as fp16 G stage (64 rows x 384B),
// buf1 (first 16KB) as f32 out stage (last step only).
#define SB_OFF   65536
#define SB_BUF   24576
#define SH_STG   (SB_OFF + SB_BUF)
#define RNN_SMEM 114688     // 112KB -> 2 CTAs/SM

// ---------------- proj kernel ----------------
#define TILE_M  64
#define NTOT    192
#define BK      64
#define NCHUNK  (KDIM / BK)
#define AS      72
#define BS      72
#define ABUF    (TILE_M * AS)
#define BBUF    (NTOT * BS)
#define BUFF    (ABUF + BBUF)
#define PROJ_SMEM (3 * BUFF * 2)    // 110592
#define SG_OFF  0                   // proj G staging: 64 rows x 384B, XOR-swizzled

// Scratch (allocation-free rule: device globals)
__device__ __half g_Gh[R_TOTAL * G3];       // input projections incl. b_ih (fp16)
__device__ __half g_Xh[R_TOTAL * KDIM];     // fp16 x
__device__ __half g_Wih_h[G3 * KDIM];       // fp16 W_ih
__device__ __half g_Whh_h[G3 * KDIM];       // fp16 W_hh

// ---------------------------------------------------------------------------
// helpers
// ---------------------------------------------------------------------------
__device__ __forceinline__ uint32_t smem_u32(const void* p) {
    uint32_t a;
    asm("{ .reg .u64 t; cvta.to.shared.u64 t, %1; cvt.u32.u64 %0, t; }" : "=r"(a) : "l"(p));
    return a;
}
__device__ __forceinline__ float tanh_apx(float x) {
    float y; asm("tanh.approx.f32 %0, %1;" : "=f"(y) : "f"(x)); return y;
}
__device__ __forceinline__ float sigm(float x) {
    return fmaf(tanh_apx(0.5f * x), 0.5f, 0.5f);
}
__device__ __forceinline__ uint32_t h2_bits(__half2 h) {
    uint32_t u; __builtin_memcpy(&u, &h, 4); return u;
}

#define CP_ASYNC16(dst, src) \
    asm volatile("cp.async.cg.shared.global [%0], [%1], 16;" :: "r"(dst), "l"(src) : "memory")
#define CP_COMMIT() asm volatile("cp.async.commit_group;" ::: "memory")
#define CP_WAIT(n)  asm volatile("cp.async.wait_group %0;" :: "n"(n) : "memory")

#define LDSM_X4(r0, r1, r2, r3, addr)                                        \
    asm volatile("ldmatrix.sync.aligned.m8n8.x4.shared.b16 {%0,%1,%2,%3}, [%4];" \
        : "=r"(r0), "=r"(r1), "=r"(r2), "=r"(r3) : "r"(addr))

__device__ __forceinline__ void mma_f16(float* d, const uint32_t* a, uint32_t b0, uint32_t b1) {
    asm volatile(
        "mma.sync.aligned.m16n8k16.row.col.f32.f16.f16.f32 "
        "{%0,%1,%2,%3}, {%4,%5,%6,%7}, {%8,%9}, {%0,%1,%2,%3};"
        : "+f"(d[0]), "+f"(d[1]), "+f"(d[2]), "+f"(d[3])
        : "r"(a[0]), "r"(a[1]), "r"(a[2]), "r"(a[3]), "r"(b0), "r"(b1));
}

// ---------------------------------------------------------------------------
// prep: convert x, W_ih, W_hh to fp16 (RN), float4-vectorized
// ---------------------------------------------------------------------------
__global__ __launch_bounds__(256) void prep_kernel(
    const float* __restrict__ x,
    const float* __restrict__ Wih,
    const float* __restrict__ Whh)
{
    int i = (blockIdx.x * 256 + threadIdx.x) * 4;
    if (i < R_TOTAL * KDIM) {
        float4 v = *(const float4*)&x[i];
        uint2 o;
        o.x = h2_bits(__floats2half2_rn(v.x, v.y));
        o.y = h2_bits(__floats2half2_rn(v.z, v.w));
        *(uint2*)&g_Xh[i] = o;
    }
    if (i < G3 * KDIM) {
        float4 v = *(const float4*)&Wih[i];
        uint2 o;
        o.x = h2_bits(__floats2half2_rn(v.x, v.y));
        o.y = h2_bits(__floats2half2_rn(v.z, v.w));
        *(uint2*)&g_Wih_h[i] = o;
        float4 w = *(const float4*)&Whh[i];
        o.x = h2_bits(__floats2half2_rn(w.x, w.y));
        o.y = h2_bits(__floats2half2_rn(w.z, w.w));
        *(uint2*)&g_Whh_h[i] = o;
    }
}

// ---------------------------------------------------------------------------
// proj kernel: G = x @ W_ih^T + b_ih  -> g_Gh (fp16), staged coalesced store
// ---------------------------------------------------------------------------
__global__ __launch_bounds__(THREADS, 2) void proj_kernel(const float* __restrict__ bih)
{
    extern __shared__ __half smf[];
    char* const smc = (char*)smf;
    const uint32_t sb = smem_u32(smf);
    const int tid = threadIdx.x;
    const int lane = tid & 31, wid = tid >> 5;
    const int warp_m = wid & 1, wn = wid >> 1;
    const int gm = blockIdx.x * TILE_M;
    const int n0 = blockIdx.y * 64;

    float acc[3][2][2][4];
#pragma unroll
    for (int g = 0; g < 3; g++)
#pragma unroll
        for (int mt = 0; mt < 2; mt++)
#pragma unroll
            for (int nt = 0; nt < 2; nt++)
#pragma unroll
                for (int e = 0; e < 4; e++) acc[g][mt][nt][e] = 0.0f;

    auto issue = [&](int k0, int buf) {
        const uint32_t abase = sb + buf * (BUFF * 2);
#pragma unroll
        for (int i = 0; i < 2; i++) {
            int j = tid + i * THREADS;
            int row = j >> 3, kv = (j & 7) << 3;
            CP_ASYNC16(abase + (row * AS + kv) * 2,
                       &g_Xh[(size_t)(gm + row) * KDIM + k0 + kv]);
        }
        const uint32_t bbase = abase + ABUF * 2;
#pragma unroll
        for (int i = 0; i < 6; i++) {
            int j = tid + i * THREADS;
            int row = j >> 3, kv = (j & 7) << 3;
            int g = row >> 6, nl = row & 63;
            CP_ASYNC16(bbase + (row * BS + kv) * 2,
                       &g_Wih_h[(size_t)(g * H_DIM + n0 + nl) * KDIM + k0 + kv]);
        }
        CP_COMMIT();
    };

    const int lr8  = lane & 7;
    const int lbit = (lane >> 3) & 1;
    const int lhi  = lane >> 4;

    issue(0, 0);
    issue(BK, 1);
#pragma unroll 1
    for (int c = 0; c < NCHUNK; c++) {
        if (c == NCHUNK - 1) { CP_WAIT(0); } else { CP_WAIT(1); }
        __syncthreads();
        if (c + 2 < NCHUNK) issue((c + 2) * BK, (c + 2) % 3);

        const uint32_t sA = sb + (c % 3) * (BUFF * 2);
        const uint32_t sB = sA + ABUF * 2;
#pragma unroll
        for (int ks = 0; ks < 4; ks++) {
            const int kk = ks * 16;
            uint32_t a[2][4];
#pragma unroll
            for (int mt = 0; mt < 2; mt++) {
                int row = warp_m * 32 + mt * 16 + lr8 + 8 * lbit;
                int col = kk + 8 * lhi;
                LDSM_X4(a[mt][0], a[mt][1], a[mt][2], a[mt][3],
                        sA + (row * AS + col) * 2);
            }
#pragma unroll
            for (int g = 0; g < 3; g++) {
                uint32_t b[4];
                int row = g * 64 + wn * 16 + lr8 + 8 * lhi;
                int col = kk + 8 * lbit;
                LDSM_X4(b[0], b[1], b[2], b[3], sB + (row * BS + col) * 2);
#pragma unroll
                for (int mt = 0; mt < 2; mt++) {
                    mma_f16(acc[g][mt][0], a[mt], b[0], b[1]);
                    mma_f16(acc[g][mt][1], a[mt], b[2], b[3]);
                }
            }
        }
    }
    __syncthreads();

    const int rl = lane >> 2, cl = (lane & 3) * 2;
    const int colb = wn * 16;
#pragma unroll
    for (int mt = 0; mt < 2; mt++)
#pragma unroll
        for (int rp = 0; rp < 2; rp++) {
            int rloc = warp_m * 32 + mt * 16 + rp * 8 + rl;
            int sw = (rloc & 7) << 4;
#pragma unroll
            for (int g = 0; g < 3; g++)
#pragma unroll
                for (int nt = 0; nt < 2; nt++) {
                    int cloc = colb + nt * 8 + cl;
                    float2 bv = *(const float2*)&bih[g * H_DIM + n0 + cloc];
                    int b = (g * 64 + cloc) * 2;
                    *(__half2*)(smc + SG_OFF + rloc * 384 + ((b & ~15) ^ sw) + (b & 15)) =
                        __floats2half2_rn(acc[g][mt][nt][rp * 2 + 0] + bv.x,
                                          acc[g][mt][nt][rp * 2 + 1] + bv.y);
                }
        }
    __syncthreads();
    for (int j = tid; j < 64 * 24; j += THREADS) {
        int r = j / 24, c = j % 24;
        int g = c >> 3, q = c & 7;
        uint4 v = *(const uint4*)(smc + SG_OFF + r * 384 + ((c * 16) ^ ((r & 7) << 4)));
        *(uint4*)&g_Gh[(size_t)(gm + r) * G3 + g * H_DIM + n0 + q * 8] = v;
    }
}

// ---------------------------------------------------------------------------
// Persistent RNN kernel: one CTA owns 64 rows x ALL 768 gate cols; the h
// recurrence state lives ONLY in smem as fp16 (double-buffered).
// ---------------------------------------------------------------------------
__global__ __launch_bounds__(THREADS, 2) void rnn_kernel(
    const float* __restrict__ bih,
    const float* __restrict__ bhh,
    float* __restrict__ fin)
{
    extern __shared__ char smc[];
    const uint32_t sb = smem_u32(smc);
    const int tid = threadIdx.x;
    const int lane = tid & 31, wid = tid >> 5;
    const int warp_m = wid & 1, wn = wid >> 1;
    const int gm = blockIdx.x * 64;
    const int gmL = gm & (L_DIM - 1);

    const int lr8  = lane & 7;
    const int lbit = (lane >> 3) & 1;
    const int lhi  = lane >> 4;
    const int rl = lane >> 2, cl = (lane & 3) * 2;
    const int colb = wn * 16;

    // ---- t = 0: h0 from G (h starts at zero) -> HH0 (fp16) ----
    for (int j = tid; j < 64 * 128; j += THREADS) {
        int r = j >> 7;
        int cp = (j & 127) * 2;
        int grow = gm + r;
        bool valid = (gmL + r - (KWIN - 1)) >= 0;
        float2 gir, giz, gin;
        if (valid) {
            const __half* Gp = &g_Gh[(size_t)(grow - (KWIN - 1)) * G3];
            gir = __half22float2(*(const __half2*)&Gp[cp]);
            giz = __half22float2(*(const __half2*)&Gp[H_DIM + cp]);
            gin = __half22float2(*(const __half2*)&Gp[2 * H_DIM + cp]);
        } else {
            gir = *(const float2*)&bih[cp];
            giz = *(const float2*)&bih[H_DIM + cp];
            gin = *(const float2*)&bih[2 * H_DIM + cp];
        }
        float2 br = *(const float2*)&bhh[cp];
        float2 bz = *(const float2*)&bhh[H_DIM + cp];
        float2 bn = *(const float2*)&bhh[2 * H_DIM + cp];
        float2 o;
        {
            float rr = sigm(gir.x + br.x);
            float zz = sigm(giz.x + bz.x);
            float nn = tanh_apx(gin.x + rr * bn.x);
            o.x = (1.0f - zz) * nn;
        }
        {
            float rr = sigm(gir.y + br.y);
            float zz = sigm(giz.y + bz.y);
            float nn = tanh_apx(gin.y + rr * bn.y);
            o.y = (1.0f - zz) * nn;
        }
        *(__half2*)(smc + HH_OFF + r * 512 + ((cp * 2) ^ ((r & 7) << 4))) =
            __float22half2_rn(o);
    }
    __syncthreads();

    // ---- steps t = 1..15 ----
#pragma unroll 1
    for (int t = 1; t < KWIN; t++) {
        const int cur = (t - 1) & 1;
        const int nxt = t & 1;
        const int t0 = t - (KWIN - 1);
        const bool last = (t == KWIN - 1);
        const uint32_t sA = sb + HH_OFF + cur * HH_BUF;

#pragma unroll 1
        for (int nc = 0; nc < 4; nc++) {
            const int n0 = nc * 64;

            float acc[3][2][2][4];
#pragma unroll
            for (int g = 0; g < 3; g++)
#pragma unroll
                for (int mt = 0; mt < 2; mt++)
#pragma unroll
                    for (int nt = 0; nt < 2; nt++)
#pragma unroll
                        for (int e = 0; e < 4; e++) acc[g][mt][nt][e] = 0.0f;

            auto issueB = [&](int kc, int buf) {
                const uint32_t bbase = sb + SB_OFF + buf * SB_BUF;
#pragma unroll
                for (int i = 0; i < 6; i++) {
                    int j = tid + i * THREADS;
                    int row = j >> 3, q = j & 7;
                    int g = row >> 6, nl = row & 63;
                    CP_ASYNC16(bbase + row * 128 + ((q * 16) ^ ((row & 7) << 4)),
                               &g_Whh_h[(size_t)(g * H_DIM + n0 + nl) * KDIM + kc * 64 + q * 8]);
                }
                CP_COMMIT();
            };
            // fp16 G stage into buf0 region (issued during kc=3 MMAs)
            auto issueG = [&]() {
#pragma unroll
                for (int i = 0; i < 6; i++) {
                    int j = tid + i * THREADS;           // 0..1535
                    int r = j / 24, c = j % 24;
                    int g = c >> 3, q = c & 7;
                    if (gmL + r + t0 >= 0)
                        CP_ASYNC16(sb + SB_OFF + r * 384 + ((c * 16) ^ ((r & 7) << 4)),
                                   &g_Gh[(size_t)(gm + r + t0) * G3 + g * H_DIM + n0 + q * 8]);
                }
                CP_COMMIT();
            };

            issueB(0, 0);
#pragma unroll 1
            for (int kc = 0; kc < 4; kc++) {
                CP_WAIT(0);
                __syncthreads();
                if (kc < 3) issueB(kc + 1, (kc + 1) & 1);
                else        issueG();
                const uint32_t sBb = sb + SB_OFF + (kc & 1) * SB_BUF;
#pragma unroll
                for (int ks = 0; ks < 4; ks++) {
                    uint32_t a[2][4];
#pragma unroll
                    for (int mt = 0; mt < 2; mt++) {
                        int row = warp_m * 32 + mt * 16 + lr8 + 8 * lbit;
                        int kbyte = kc * 128 + ks * 32 + lhi * 16;
                        LDSM_X4(a[mt][0], a[mt][1], a[mt][2], a[mt][3],
                                sA + row * 512 + (kbyte ^ ((row & 7) << 4)));
                    }
#pragma unroll
                    for (int g = 0; g < 3; g++) {
                        uint32_t b[4];
                        int row = g * 64 + wn * 16 + lr8 + 8 * lhi;
                        int kbyte = ks * 32 + lbit * 16;
                        LDSM_X4(b[0], b[1], b[2], b[3],
                                sBb + row * 128 + (kbyte ^ ((row & 7) << 4)));
#pragma unroll
                        for (int mt = 0; mt < 2; mt++) {
                            mma_f16(acc[g][mt][0], a[mt], b[0], b[1]);
                            mma_f16(acc[g][mt][1], a[mt], b[2], b[3]);
                        }
                    }
                }
            }
            CP_WAIT(0);        // G stage arrival
            __syncthreads();

            // GRU epilogue: G from staged smem, h (fp16) from resident HH cur
#pragma unroll
            for (int mt = 0; mt < 2; mt++)
#pragma unroll
                for (int rp = 0; rp < 2; rp++) {
                    int rloc = warp_m * 32 + mt * 16 + rp * 8 + rl;
                    bool valid = (gmL + rloc + t0) >= 0;
                    int sw = (rloc & 7) << 4;
#pragma unroll
                    for (int nt = 0; nt < 2; nt++) {
                        int cloc = colb + nt * 8 + cl;
                        int col = n0 + cloc;
                        float2 gr, gz, gn;
                        if (valid) {
                            const char* gp = smc + SB_OFF + rloc * 384;
#pragma unroll
                            for (int g = 0; g < 3; g++) {
                                int b = (g * 64 + cloc) * 2;
                                float2 v = __half22float2(
                                    *(const __half2*)(gp + ((b & ~15) ^ sw) + (b & 15)));
                                if (g == 0) gr = v; else if (g == 1) gz = v; else gn = v;
                            }
                        } else {
                            gr = *(const float2*)&bih[col];
                            gz = *(const float2*)&bih[H_DIM + col];
                            gn = *(const float2*)&bih[2 * H_DIM + col];
                        }
                        float2 br = *(const float2*)&bhh[col];
                        float2 bz = *(const float2*)&bhh[H_DIM + col];
                        float2 bn = *(const float2*)&bhh[2 * H_DIM + col];
                        float2 h = __half22float2(*(const __half2*)(
                            smc + HH_OFF + cur * HH_BUF + rloc * 512 + ((col * 2) ^ sw)));
                        float2 o;
                        {
                            float r  = sigm(gr.x + acc[0][mt][nt][rp * 2] + br.x);
                            float z  = sigm(gz.x + acc[1][mt][nt][rp * 2] + bz.x);
                            float nn = tanh_apx(gn.x + r * (acc[2][mt][nt][rp * 2] + bn.x));
                            o.x = (1.0f - z) * nn + z * h.x;
                        }
                        {
                            float r  = sigm(gr.y + acc[0][mt][nt][rp * 2 + 1] + br.y);
                            float z  = sigm(gz.y + acc[1][mt][nt][rp * 2 + 1] + bz.y);
                            float nn = tanh_apx(gn.y + r * (acc[2][mt][nt][rp * 2 + 1] + bn.y));
                            o.y = (1.0f - z) * nn + z * h.y;
                        }
                        if (last) {
                            int hb = cloc * 4;
                            *(float2*)(smc + SH_STG + rloc * 256 + ((hb & ~15) ^ sw) + (hb & 15)) = o;
                        } else {
                            *(__half2*)(smc + HH_OFF + nxt * HH_BUF + rloc * 512 +
                                        ((col * 2) ^ sw)) = __float22half2_rn(o);
                        }
                    }
                }
            __syncthreads();   // G-stage region freed before next nc's B loads

            if (last) {        // coalesced final store
#pragma unroll
                for (int i = 0; i < 4; i++) {
                    int j = tid + i * THREADS;
                    int r = j >> 4, q = j & 15;
                    float4 v = *(const float4*)(smc + SH_STG + r * 256 +
                                                ((q * 16) ^ ((r & 7) << 4)));
                    *(float4*)&fin[(size_t)(gm + r) * H_DIM + n0 + q * 4] = v;
                }
                __syncthreads();
            }
        }
    }
}

// ---------------------------------------------------------------------------
// Launch: prep -> proj -> persistent rnn (3 launches total)
// ---------------------------------------------------------------------------
extern "C" void kernel_launch(void* const* d_in, const int* in_sizes, int n_in,
                              void* d_out, int out_size)
{
    const float* x   = (const float*)d_in[0];
    const float* Wih = (const float*)d_in[1];
    const float* Whh = (const float*)d_in[2];
    const float* bih = (const float*)d_in[3];
    const float* bhh = (const float*)d_in[4];
    float* out = (float*)d_out;

    cudaFuncSetAttribute(proj_kernel, cudaFuncAttributeMaxDynamicSharedMemorySize, PROJ_SMEM);
    cudaFuncSetAttribute(rnn_kernel,  cudaFuncAttributeMaxDynamicSharedMemorySize, RNN_SMEM);

    prep_kernel<<<(R_TOTAL * KDIM / 4 + 255) / 256, 256>>>(x, Wih, Whh);
    dim3 pgrid(R_TOTAL / TILE_M, H_DIM / 64);   // (256, 4)
    proj_kernel<<<pgrid, THREADS, PROJ_SMEM>>>(bih);
    rnn_kernel<<<R_TOTAL / 64, THREADS, RNN_SMEM>>>(bih, bhh, out);
}

// round 15
// speedup vs baseline: 2.6936x; 1.0142x over previous
#include <cuda_runtime.h>
#include <cuda_fp16.h>
#include <cstdint>

// Problem dims (fixed)
#define L_DIM   1024
#define H_DIM   256
#define KWIN    16
#define R_TOTAL 16384
#define G3      768
#define KDIM    256

// ---------------- persistent rnn kernel: M=128/CTA, 512 thr, 1 CTA/SM ------
#define THREADS_R 512
#define RTILE_M   128
// HH: fp16 H double buffer, [128 rows][256 halves] per buf, 512B/row, swizzled
#define HH_OFF   0
#define HH_BUF   65536
// SB: W_hh k-chunk ring, 3 x [192 rows][64 halves] bufs (24576B each), swizzled.
// G stage (fp16, 128 rows x 384B = 49152B) reuses bufs 1+2 late in the kc loop.
#define SB_OFF   131072
#define SB_BUF   24576
#define GS_OFF   (SB_OFF + SB_BUF)          // G stage = bufs 1+2
#define RNN_SMEM 204800                      // 200KB -> 1 CTA/SM

// ---------------- proj kernel (unchanged, M=64, 2 CTAs/SM) ----------------
#define THREADS 256
#define TILE_M  64
#define NTOT    192
#define BK      64
#define NCHUNK  (KDIM / BK)
#define AS      72
#define BS      72
#define ABUF    (TILE_M * AS)
#define BBUF    (NTOT * BS)
#define BUFF    (ABUF + BBUF)
#define PROJ_SMEM (3 * BUFF * 2)    // 110592
#define SG_OFF  0

// Scratch (allocation-free rule: device globals)
__device__ __half g_Gh[R_TOTAL * G3];       // input projections incl. b_ih (fp16)
__device__ __half g_Xh[R_TOTAL * KDIM];     // fp16 x
__device__ __half g_Wih_h[G3 * KDIM];       // fp16 W_ih
__device__ __half g_Whh_h[G3 * KDIM];       // fp16 W_hh

// ---------------------------------------------------------------------------
// helpers
// ---------------------------------------------------------------------------
__device__ __forceinline__ uint32_t smem_u32(const void* p) {
    uint32_t a;
    asm("{ .reg .u64 t; cvta.to.shared.u64 t, %1; cvt.u32.u64 %0, t; }" : "=r"(a) : "l"(p));
    return a;
}
__device__ __forceinline__ float tanh_apx(float x) {
    float y; asm("tanh.approx.f32 %0, %1;" : "=f"(y) : "f"(x)); return y;
}
__device__ __forceinline__ float sigm(float x) {
    return fmaf(tanh_apx(0.5f * x), 0.5f, 0.5f);
}
__device__ __forceinline__ uint32_t h2_bits(__half2 h) {
    uint32_t u; __builtin_memcpy(&u, &h, 4); return u;
}

#define CP_ASYNC16(dst, src) \
    asm volatile("cp.async.cg.shared.global [%0], [%1], 16;" :: "r"(dst), "l"(src) : "memory")
#define CP_COMMIT() asm volatile("cp.async.commit_group;" ::: "memory")
#define CP_WAIT(n)  asm volatile("cp.async.wait_group %0;" :: "n"(n) : "memory")

#define LDSM_X4(r0, r1, r2, r3, addr)                                        \
    asm volatile("ldmatrix.sync.aligned.m8n8.x4.shared.b16 {%0,%1,%2,%3}, [%4];" \
        : "=r"(r0), "=r"(r1), "=r"(r2), "=r"(r3) : "r"(addr))

__device__ __forceinline__ void mma_f16(float* d, const uint32_t* a, uint32_t b0, uint32_t b1) {
    asm volatile(
        "mma.sync.aligned.m16n8k16.row.col.f32.f16.f16.f32 "
        "{%0,%1,%2,%3}, {%4,%5,%6,%7}, {%8,%9}, {%0,%1,%2,%3};"
        : "+f"(d[0]), "+f"(d[1]), "+f"(d[2]), "+f"(d[3])
        : "r"(a[0]), "r"(a[1]), "r"(a[2]), "r"(a[3]), "r"(b0), "r"(b1));
}

// ---------------------------------------------------------------------------
// prep: convert x, W_ih, W_hh to fp16 (RN), float4-vectorized
// ---------------------------------------------------------------------------
__global__ __launch_bounds__(256) void prep_kernel(
    const float* __restrict__ x,
    const float* __restrict__ Wih,
    const float* __restrict__ Whh)
{
    int i = (blockIdx.x * 256 + threadIdx.x) * 4;
    if (i < R_TOTAL * KDIM) {
        float4 v = *(const float4*)&x[i];
        uint2 o;
        o.x = h2_bits(__floats2half2_rn(v.x, v.y));
        o.y = h2_bits(__floats2half2_rn(v.z, v.w));
        *(uint2*)&g_Xh[i] = o;
    }
    if (i < G3 * KDIM) {
        float4 v = *(const float4*)&Wih[i];
        uint2 o;
        o.x = h2_bits(__floats2half2_rn(v.x, v.y));
        o.y = h2_bits(__floats2half2_rn(v.z, v.w));
        *(uint2*)&g_Wih_h[i] = o;
        float4 w = *(const float4*)&Whh[i];
        o.x = h2_bits(__floats2half2_rn(w.x, w.y));
        o.y = h2_bits(__floats2half2_rn(w.z, w.w));
        *(uint2*)&g_Whh_h[i] = o;
    }
}

// ---------------------------------------------------------------------------
// proj kernel: G = x @ W_ih^T + b_ih  -> g_Gh (fp16), staged coalesced store
// ---------------------------------------------------------------------------
__global__ __launch_bounds__(THREADS, 2) void proj_kernel(const float* __restrict__ bih)
{
    extern __shared__ __half smf[];
    char* const smc = (char*)smf;
    const uint32_t sb = smem_u32(smf);
    const int tid = threadIdx.x;
    const int lane = tid & 31, wid = tid >> 5;
    const int warp_m = wid & 1, wn = wid >> 1;
    const int gm = blockIdx.x * TILE_M;
    const int n0 = blockIdx.y * 64;

    float acc[3][2][2][4];
#pragma unroll
    for (int g = 0; g < 3; g++)
#pragma unroll
        for (int mt = 0; mt < 2; mt++)
#pragma unroll
            for (int nt = 0; nt < 2; nt++)
#pragma unroll
                for (int e = 0; e < 4; e++) acc[g][mt][nt][e] = 0.0f;

    auto issue = [&](int k0, int buf) {
        const uint32_t abase = sb + buf * (BUFF * 2);
#pragma unroll
        for (int i = 0; i < 2; i++) {
            int j = tid + i * THREADS;
            int row = j >> 3, kv = (j & 7) << 3;
            CP_ASYNC16(abase + (row * AS + kv) * 2,
                       &g_Xh[(size_t)(gm + row) * KDIM + k0 + kv]);
        }
        const uint32_t bbase = abase + ABUF * 2;
#pragma unroll
        for (int i = 0; i < 6; i++) {
            int j = tid + i * THREADS;
            int row = j >> 3, kv = (j & 7) << 3;
            int g = row >> 6, nl = row & 63;
            CP_ASYNC16(bbase + (row * BS + kv) * 2,
                       &g_Wih_h[(size_t)(g * H_DIM + n0 + nl) * KDIM + k0 + kv]);
        }
        CP_COMMIT();
    };

    const int lr8  = lane & 7;
    const int lbit = (lane >> 3) & 1;
    const int lhi  = lane >> 4;

    issue(0, 0);
    issue(BK, 1);
#pragma unroll 1
    for (int c = 0; c < NCHUNK; c++) {
        if (c == NCHUNK - 1) { CP_WAIT(0); } else { CP_WAIT(1); }
        __syncthreads();
        if (c + 2 < NCHUNK) issue((c + 2) * BK, (c + 2) % 3);

        const uint32_t sA = sb + (c % 3) * (BUFF * 2);
        const uint32_t sB = sA + ABUF * 2;
#pragma unroll
        for (int ks = 0; ks < 4; ks++) {
            const int kk = ks * 16;
            uint32_t a[2][4];
#pragma unroll
            for (int mt = 0; mt < 2; mt++) {
                int row = warp_m * 32 + mt * 16 + lr8 + 8 * lbit;
                int col = kk + 8 * lhi;
                LDSM_X4(a[mt][0], a[mt][1], a[mt][2], a[mt][3],
                        sA + (row * AS + col) * 2);
            }
#pragma unroll
            for (int g = 0; g < 3; g++) {
                uint32_t b[4];
                int row = g * 64 + wn * 16 + lr8 + 8 * lhi;
                int col = kk + 8 * lbit;
                LDSM_X4(b[0], b[1], b[2], b[3], sB + (row * BS + col) * 2);
#pragma unroll
                for (int mt = 0; mt < 2; mt++) {
                    mma_f16(acc[g][mt][0], a[mt], b[0], b[1]);
                    mma_f16(acc[g][mt][1], a[mt], b[2], b[3]);
                }
            }
        }
    }
    __syncthreads();

    const int rl = lane >> 2, cl = (lane & 3) * 2;
    const int colb = wn * 16;
#pragma unroll
    for (int mt = 0; mt < 2; mt++)
#pragma unroll
        for (int rp = 0; rp < 2; rp++) {
            int rloc = warp_m * 32 + mt * 16 + rp * 8 + rl;
            int sw = (rloc & 7) << 4;
#pragma unroll
            for (int g = 0; g < 3; g++)
#pragma unroll
                for (int nt = 0; nt < 2; nt++) {
                    int cloc = colb + nt * 8 + cl;
                    float2 bv = *(const float2*)&bih[g * H_DIM + n0 + cloc];
                    int b = (g * 64 + cloc) * 2;
                    *(__half2*)(smc + SG_OFF + rloc * 384 + ((b & ~15) ^ sw) + (b & 15)) =
                        __floats2half2_rn(acc[g][mt][nt][rp * 2 + 0] + bv.x,
                                          acc[g][mt][nt][rp * 2 + 1] + bv.y);
                }
        }
    __syncthreads();
    for (int j = tid; j < 64 * 24; j += THREADS) {
        int r = j / 24, c = j % 24;
        int g = c >> 3, q = c & 7;
        uint4 v = *(const uint4*)(smc + SG_OFF + r * 384 + ((c * 16) ^ ((r & 7) << 4)));
        *(uint4*)&g_Gh[(size_t)(gm + r) * G3 + g * H_DIM + n0 + q * 8] = v;
    }
}

// ---------------------------------------------------------------------------
// Persistent RNN kernel: one CTA owns 128 rows x ALL 768 gate cols; the h
// recurrence state lives ONLY in smem as fp16 (double-buffered).
// ---------------------------------------------------------------------------
__global__ __launch_bounds__(THREADS_R, 1) void rnn_kernel(
    const float* __restrict__ bih,
    const float* __restrict__ bhh,
    float* __restrict__ fin)
{
    extern __shared__ char smc[];
    const uint32_t sb = smem_u32(smc);
    const int tid = threadIdx.x;
    const int lane = tid & 31, wid = tid >> 5;
    const int warp_m = wid & 3, wn = wid >> 2;
    const int gm = blockIdx.x * RTILE_M;
    const int gmL = gm & (L_DIM - 1);

    const int lr8  = lane & 7;
    const int lbit = (lane >> 3) & 1;
    const int lhi  = lane >> 4;
    const int rl = lane >> 2, cl = (lane & 3) * 2;
    const int colb = wn * 16;

    // ---- t = 0: h0 from G (h starts at zero) -> HH0 (fp16) ----
    for (int j = tid; j < RTILE_M * 128; j += THREADS_R) {
        int r = j >> 7;
        int cp = (j & 127) * 2;
        int grow = gm + r;
        bool valid = (gmL + r - (KWIN - 1)) >= 0;
        float2 gir, giz, gin;
        if (valid) {
            const __half* Gp = &g_Gh[(size_t)(grow - (KWIN - 1)) * G3];
            gir = __half22float2(*(const __half2*)&Gp[cp]);
            giz = __half22float2(*(const __half2*)&Gp[H_DIM + cp]);
            gin = __half22float2(*(const __half2*)&Gp[2 * H_DIM + cp]);
        } else {
            gir = *(const float2*)&bih[cp];
            giz = *(const float2*)&bih[H_DIM + cp];
            gin = *(const float2*)&bih[2 * H_DIM + cp];
        }
        float2 br = *(const float2*)&bhh[cp];
        float2 bz = *(const float2*)&bhh[H_DIM + cp];
        float2 bn = *(const float2*)&bhh[2 * H_DIM + cp];
        float2 o;
        {
            float rr = sigm(gir.x + br.x);
            float zz = sigm(giz.x + bz.x);
            float nn = tanh_apx(gin.x + rr * bn.x);
            o.x = (1.0f - zz) * nn;
        }
        {
            float rr = sigm(gir.y + br.y);
            float zz = sigm(giz.y + bz.y);
            float nn = tanh_apx(gin.y + rr * bn.y);
            o.y = (1.0f - zz) * nn;
        }
        *(__half2*)(smc + HH_OFF + r * 512 + ((cp * 2) ^ ((r & 7) << 4))) =
            __float22half2_rn(o);
    }
    __syncthreads();

    // ---- steps t = 1..15 ----
#pragma unroll 1
    for (int t = 1; t < KWIN; t++) {
        const int cur = (t - 1) & 1;
        const int nxt = t & 1;
        const int t0 = t - (KWIN - 1);
        const bool last = (t == KWIN - 1);
        const uint32_t sA = sb + HH_OFF + cur * HH_BUF;

#pragma unroll 1
        for (int nc = 0; nc < 4; nc++) {
            const int n0 = nc * 64;

            float acc[3][2][2][4];
#pragma unroll
            for (int g = 0; g < 3; g++)
#pragma unroll
                for (int mt = 0; mt < 2; mt++)
#pragma unroll
                    for (int nt = 0; nt < 2; nt++)
#pragma unroll
                        for (int e = 0; e < 4; e++) acc[g][mt][nt][e] = 0.0f;

            auto issueB = [&](int kc, int buf) {
                const uint32_t bbase = sb + SB_OFF + buf * SB_BUF;
#pragma unroll
                for (int i = 0; i < 3; i++) {            // 1536 chunks / 512 thr
                    int j = tid + i * THREADS_R;
                    int row = j >> 3, q = j & 7;
                    int g = row >> 6, nl = row & 63;
                    CP_ASYNC16(bbase + row * 128 + ((q * 16) ^ ((row & 7) << 4)),
                               &g_Whh_h[(size_t)(g * H_DIM + n0 + nl) * KDIM + kc * 64 + q * 8]);
                }
                CP_COMMIT();
            };
            // fp16 G stage halves into GS (bufs 1+2), row half = 0 or 1
            auto issueG = [&](int half) {
#pragma unroll
                for (int i = 0; i < 3; i++) {            // 1536 chunks per half
                    int j = tid + i * THREADS_R;
                    int r = half * 64 + j / 24;
                    int c = j % 24;
                    int g = c >> 3, q = c & 7;
                    if (gmL + r + t0 >= 0)
                        CP_ASYNC16(sb + GS_OFF + r * 384 + ((c * 16) ^ ((r & 7) << 4)),
                                   &g_Gh[(size_t)(gm + r + t0) * G3 + g * H_DIM + n0 + q * 8]);
                }
                CP_COMMIT();
            };

            issueB(0, 0);
            issueB(1, 1);
#pragma unroll 1
            for (int kc = 0; kc < 4; kc++) {
                CP_WAIT(1);
                __syncthreads();
                if (kc == 0)      issueB(2, 2);
                else if (kc == 1) issueB(3, 0);
                else if (kc == 2) issueG(0);   // -> buf1 region (rows 0..63)
                else              issueG(1);   // -> buf2 region (rows 64..127)
                const uint32_t sBb = sb + SB_OFF + (kc % 3) * SB_BUF;
#pragma unroll
                for (int ks = 0; ks < 4; ks++) {
                    uint32_t a[2][4];
#pragma unroll
                    for (int mt = 0; mt < 2; mt++) {
                        int row = warp_m * 32 + mt * 16 + lr8 + 8 * lbit;
                        int kbyte = kc * 128 + ks * 32 + lhi * 16;
                        LDSM_X4(a[mt][0], a[mt][1], a[mt][2], a[mt][3],
                                sA + row * 512 + (kbyte ^ ((row & 7) << 4)));
                    }
#pragma unroll
                    for (int g = 0; g < 3; g++) {
                        uint32_t b[4];
                        int row = g * 64 + wn * 16 + lr8 + 8 * lhi;
                        int kbyte = ks * 32 + lbit * 16;
                        LDSM_X4(b[0], b[1], b[2], b[3],
                                sBb + row * 128 + (kbyte ^ ((row & 7) << 4)));
#pragma unroll
                        for (int mt = 0; mt < 2; mt++) {
                            mma_f16(acc[g][mt][0], a[mt], b[0], b[1]);
                            mma_f16(acc[g][mt][1], a[mt], b[2], b[3]);
                        }
                    }
                }
            }
            CP_WAIT(0);        // both G halves arrived
            __syncthreads();

            // GRU epilogue: G from staged smem, h (fp16) from resident HH cur
#pragma unroll
            for (int mt = 0; mt < 2; mt++)
#pragma unroll
                for (int rp = 0; rp < 2; rp++) {
                    int rloc = warp_m * 32 + mt * 16 + rp * 8 + rl;
                    bool valid = (gmL + rloc + t0) >= 0;
                    int sw = (rloc & 7) << 4;
#pragma unroll
                    for (int nt = 0; nt < 2; nt++) {
                        int cloc = colb + nt * 8 + cl;
                        int col = n0 + cloc;
                        float2 gr, gz, gn;
                        if (valid) {
                            const char* gp = smc + GS_OFF + rloc * 384;
#pragma unroll
                            for (int g = 0; g < 3; g++) {
                                int b = (g * 64 + cloc) * 2;
                                float2 v = __half22float2(
                                    *(const __half2*)(gp + ((b & ~15) ^ sw) + (b & 15)));
                                if (g == 0) gr = v; else if (g == 1) gz = v; else gn = v;
                            }
                        } else {
                            gr = *(const float2*)&bih[col];
                            gz = *(const float2*)&bih[H_DIM + col];
                            gn = *(const float2*)&bih[2 * H_DIM + col];
                        }
                        float2 br = *(const float2*)&bhh[col];
                        float2 bz = *(const float2*)&bhh[H_DIM + col];
                        float2 bn = *(const float2*)&bhh[2 * H_DIM + col];
                        float2 h = __half22float2(*(const __half2*)(
                            smc + HH_OFF + cur * HH_BUF + rloc * 512 + ((col * 2) ^ sw)));
                        float2 o;
                        {
                            float r  = sigm(gr.x + acc[0][mt][nt][rp * 2] + br.x);
                            float z  = sigm(gz.x + acc[1][mt][nt][rp * 2] + bz.x);
                            float nn = tanh_apx(gn.x + r * (acc[2][mt][nt][rp * 2] + bn.x));
                            o.x = (1.0f - z) * nn + z * h.x;
                        }
                        {
                            float r  = sigm(gr.y + acc[0][mt][nt][rp * 2 + 1] + br.y);
                            float z  = sigm(gz.y + acc[1][mt][nt][rp * 2 + 1] + bz.y);
                            float nn = tanh_apx(gn.y + r * (acc[2][mt][nt][rp * 2 + 1] + bn.y));
                            o.y = (1.0f - z) * nn + z * h.y;
                        }
                        if (last) {
                            // stage f32 out in the (unused) HH nxt buffer
                            int hb = cloc * 4;
                            *(float2*)(smc + HH_OFF + nxt * HH_BUF + rloc * 256 +
                                       ((hb & ~15) ^ sw) + (hb & 15)) = o;
                        } else {
                            *(__half2*)(smc + HH_OFF + nxt * HH_BUF + rloc * 512 +
                                        ((col * 2) ^ sw)) = __float22half2_rn(o);
                        }
                    }
                }
            __syncthreads();   // G-stage region freed before next nc's B loads

            if (last) {        // coalesced final store
#pragma unroll
                for (int i = 0; i < 4; i++) {
                    int j = tid + i * THREADS_R;         // 2048 float4
                    int r = j >> 4, q = j & 15;
                    float4 v = *(const float4*)(smc + HH_OFF + nxt * HH_BUF + r * 256 +
                                                ((q * 16) ^ ((r & 7) << 4)));
                    *(float4*)&fin[(size_t)(gm + r) * H_DIM + n0 + q * 4] = v;
                }
                __syncthreads();
            }
        }
    }
}

// ---------------------------------------------------------------------------
// Launch: prep -> proj -> persistent rnn (3 launches total)
// ---------------------------------------------------------------------------
extern "C" void kernel_launch(void* const* d_in, const int* in_sizes, int n_in,
                              void* d_out, int out_size)
{
    const float* x   = (const float*)d_in[0];
    const float* Wih = (const float*)d_in[1];
    const float* Whh = (const float*)d_in[2];
    const float* bih = (const float*)d_in[3];
    const float* bhh = (const float*)d_in[4];
    float* out = (float*)d_out;

    cudaFuncSetAttribute(proj_kernel, cudaFuncAttributeMaxDynamicSharedMemorySize, PROJ_SMEM);
    cudaFuncSetAttribute(rnn_kernel,  cudaFuncAttributeMaxDynamicSharedMemorySize, RNN_SMEM);

    prep_kernel<<<(R_TOTAL * KDIM / 4 + 255) / 256, 256>>>(x, Wih, Whh);
    dim3 pgrid(R_TOTAL / TILE_M, H_DIM / 64);   // (256, 4)
    proj_kernel<<<pgrid, THREADS, PROJ_SMEM>>>(bih);
    rnn_kernel<<<R_TOTAL / RTILE_M, THREADS_R, RNN_SMEM>>>(bih, bhh, out);
}

// round 16
// speedup vs baseline: 2.8461x; 1.0566x over previous
#include <cuda_runtime.h>
#include <cuda_fp16.h>
#include <cstdint>

// Problem dims (fixed)
#define L_DIM   1024
#define H_DIM   256
#define KWIN    16
#define R_TOTAL 16384
#define G3      768
#define KDIM    256

// ---------------- persistent rnn kernel: M=128/CTA, 512 thr, 1 CTA/SM ------
#define THREADS_R 512
#define RTILE_M   128
// HH: fp16 H double buffer, [128 rows][256 halves] per buf, 512B/row, swizzled
#define HH_OFF   0
#define HH_BUF   65536
// W ring: 2 x [192 rows][128 halves] bufs (49152B each, 256B/row, swizzled).
// Per nc: kb0 in buf fb, kb1 in buf 1-fb (fb = nc&1). G stage (fp16, 128 rows
// x 384B = 49152B) reuses the kb0 buffer after it drains.
#define SB_OFF   131072
#define WBUF     49152
#define RNN_SMEM 229376     // 224KB -> 1 CTA/SM

// ---------------- proj kernel (unchanged, M=64, 2 CTAs/SM) ----------------
#define THREADS 256
#define TILE_M  64
#define NTOT    192
#define BK      64
#define NCHUNK  (KDIM / BK)
#define AS      72
#define BS      72
#define ABUF    (TILE_M * AS)
#define BBUF    (NTOT * BS)
#define BUFF    (ABUF + BBUF)
#define PROJ_SMEM (3 * BUFF * 2)    // 110592
#define SG_OFF  0

// Scratch (allocation-free rule: device globals)
__device__ __half g_Gh[R_TOTAL * G3];       // input projections incl. b_ih (fp16)
__device__ __half g_Xh[R_TOTAL * KDIM];     // fp16 x
__device__ __half g_Wih_h[G3 * KDIM];       // fp16 W_ih
__device__ __half g_Whh_h[G3 * KDIM];       // fp16 W_hh

// ---------------------------------------------------------------------------
// helpers
// ---------------------------------------------------------------------------
__device__ __forceinline__ uint32_t smem_u32(const void* p) {
    uint32_t a;
    asm("{ .reg .u64 t; cvta.to.shared.u64 t, %1; cvt.u32.u64 %0, t; }" : "=r"(a) : "l"(p));
    return a;
}
__device__ __forceinline__ float tanh_apx(float x) {
    float y; asm("tanh.approx.f32 %0, %1;" : "=f"(y) : "f"(x)); return y;
}
__device__ __forceinline__ float sigm(float x) {
    return fmaf(tanh_apx(0.5f * x), 0.5f, 0.5f);
}
__device__ __forceinline__ uint32_t h2_bits(__half2 h) {
    uint32_t u; __builtin_memcpy(&u, &h, 4); return u;
}

#define CP_ASYNC16(dst, src) \
    asm volatile("cp.async.cg.shared.global [%0], [%1], 16;" :: "r"(dst), "l"(src) : "memory")
#define CP_COMMIT() asm volatile("cp.async.commit_group;" ::: "memory")
#define CP_WAIT(n)  asm volatile("cp.async.wait_group %0;" :: "n"(n) : "memory")

#define LDSM_X4(r0, r1, r2, r3, addr)                                        \
    asm volatile("ldmatrix.sync.aligned.m8n8.x4.shared.b16 {%0,%1,%2,%3}, [%4];" \
        : "=r"(r0), "=r"(r1), "=r"(r2), "=r"(r3) : "r"(addr))

__device__ __forceinline__ void mma_f16(float* d, const uint32_t* a, uint32_t b0, uint32_t b1) {
    asm volatile(
        "mma.sync.aligned.m16n8k16.row.col.f32.f16.f16.f32 "
        "{%0,%1,%2,%3}, {%4,%5,%6,%7}, {%8,%9}, {%0,%1,%2,%3};"
        : "+f"(d[0]), "+f"(d[1]), "+f"(d[2]), "+f"(d[3])
        : "r"(a[0]), "r"(a[1]), "r"(a[2]), "r"(a[3]), "r"(b0), "r"(b1));
}

// ---------------------------------------------------------------------------
// prep: convert x, W_ih, W_hh to fp16 (RN), float4-vectorized
// ---------------------------------------------------------------------------
__global__ __launch_bounds__(256) void prep_kernel(
    const float* __restrict__ x,
    const float* __restrict__ Wih,
    const float* __restrict__ Whh)
{
    int i = (blockIdx.x * 256 + threadIdx.x) * 4;
    if (i < R_TOTAL * KDIM) {
        float4 v = *(const float4*)&x[i];
        uint2 o;
        o.x = h2_bits(__floats2half2_rn(v.x, v.y));
        o.y = h2_bits(__floats2half2_rn(v.z, v.w));
        *(uint2*)&g_Xh[i] = o;
    }
    if (i < G3 * KDIM) {
        float4 v = *(const float4*)&Wih[i];
        uint2 o;
        o.x = h2_bits(__floats2half2_rn(v.x, v.y));
        o.y = h2_bits(__floats2half2_rn(v.z, v.w));
        *(uint2*)&g_Wih_h[i] = o;
        float4 w = *(const float4*)&Whh[i];
        o.x = h2_bits(__floats2half2_rn(w.x, w.y));
        o.y = h2_bits(__floats2half2_rn(w.z, w.w));
        *(uint2*)&g_Whh_h[i] = o;
    }
}

// ---------------------------------------------------------------------------
// proj kernel: G = x @ W_ih^T + b_ih  -> g_Gh (fp16), staged coalesced store
// ---------------------------------------------------------------------------
__global__ __launch_bounds__(THREADS, 2) void proj_kernel(const float* __restrict__ bih)
{
    extern __shared__ __half smf[];
    char* const smc = (char*)smf;
    const uint32_t sb = smem_u32(smf);
    const int tid = threadIdx.x;
    const int lane = tid & 31, wid = tid >> 5;
    const int warp_m = wid & 1, wn = wid >> 1;
    const int gm = blockIdx.x * TILE_M;
    const int n0 = blockIdx.y * 64;

    float acc[3][2][2][4];
#pragma unroll
    for (int g = 0; g < 3; g++)
#pragma unroll
        for (int mt = 0; mt < 2; mt++)
#pragma unroll
            for (int nt = 0; nt < 2; nt++)
#pragma unroll
                for (int e = 0; e < 4; e++) acc[g][mt][nt][e] = 0.0f;

    auto issue = [&](int k0, int buf) {
        const uint32_t abase = sb + buf * (BUFF * 2);
#pragma unroll
        for (int i = 0; i < 2; i++) {
            int j = tid + i * THREADS;
            int row = j >> 3, kv = (j & 7) << 3;
            CP_ASYNC16(abase + (row * AS + kv) * 2,
                       &g_Xh[(size_t)(gm + row) * KDIM + k0 + kv]);
        }
        const uint32_t bbase = abase + ABUF * 2;
#pragma unroll
        for (int i = 0; i < 6; i++) {
            int j = tid + i * THREADS;
            int row = j >> 3, kv = (j & 7) << 3;
            int g = row >> 6, nl = row & 63;
            CP_ASYNC16(bbase + (row * BS + kv) * 2,
                       &g_Wih_h[(size_t)(g * H_DIM + n0 + nl) * KDIM + k0 + kv]);
        }
        CP_COMMIT();
    };

    const int lr8  = lane & 7;
    const int lbit = (lane >> 3) & 1;
    const int lhi  = lane >> 4;

    issue(0, 0);
    issue(BK, 1);
#pragma unroll 1
    for (int c = 0; c < NCHUNK; c++) {
        if (c == NCHUNK - 1) { CP_WAIT(0); } else { CP_WAIT(1); }
        __syncthreads();
        if (c + 2 < NCHUNK) issue((c + 2) * BK, (c + 2) % 3);

        const uint32_t sA = sb + (c % 3) * (BUFF * 2);
        const uint32_t sB = sA + ABUF * 2;
#pragma unroll
        for (int ks = 0; ks < 4; ks++) {
            const int kk = ks * 16;
            uint32_t a[2][4];
#pragma unroll
            for (int mt = 0; mt < 2; mt++) {
                int row = warp_m * 32 + mt * 16 + lr8 + 8 * lbit;
                int col = kk + 8 * lhi;
                LDSM_X4(a[mt][0], a[mt][1], a[mt][2], a[mt][3],
                        sA + (row * AS + col) * 2);
            }
#pragma unroll
            for (int g = 0; g < 3; g++) {
                uint32_t b[4];
                int row = g * 64 + wn * 16 + lr8 + 8 * lhi;
                int col = kk + 8 * lbit;
                LDSM_X4(b[0], b[1], b[2], b[3], sB + (row * BS + col) * 2);
#pragma unroll
                for (int mt = 0; mt < 2; mt++) {
                    mma_f16(acc[g][mt][0], a[mt], b[0], b[1]);
                    mma_f16(acc[g][mt][1], a[mt], b[2], b[3]);
                }
            }
        }
    }
    __syncthreads();

    const int rl = lane >> 2, cl = (lane & 3) * 2;
    const int colb = wn * 16;
#pragma unroll
    for (int mt = 0; mt < 2; mt++)
#pragma unroll
        for (int rp = 0; rp < 2; rp++) {
            int rloc = warp_m * 32 + mt * 16 + rp * 8 + rl;
            int sw = (rloc & 7) << 4;
#pragma unroll
            for (int g = 0; g < 3; g++)
#pragma unroll
                for (int nt = 0; nt < 2; nt++) {
                    int cloc = colb + nt * 8 + cl;
                    float2 bv = *(const float2*)&bih[g * H_DIM + n0 + cloc];
                    int b = (g * 64 + cloc) * 2;
                    *(__half2*)(smc + SG_OFF + rloc * 384 + ((b & ~15) ^ sw) + (b & 15)) =
                        __floats2half2_rn(acc[g][mt][nt][rp * 2 + 0] + bv.x,
                                          acc[g][mt][nt][rp * 2 + 1] + bv.y);
                }
        }
    __syncthreads();
    for (int j = tid; j < 64 * 24; j += THREADS) {
        int r = j / 24, c = j % 24;
        int g = c >> 3, q = c & 7;
        uint4 v = *(const uint4*)(smc + SG_OFF + r * 384 + ((c * 16) ^ ((r & 7) << 4)));
        *(uint4*)&g_Gh[(size_t)(gm + r) * G3 + g * H_DIM + n0 + q * 8] = v;
    }
}

// ---------------------------------------------------------------------------
// Persistent RNN kernel: one CTA owns 128 rows x ALL 768 gate cols; h state
// lives ONLY in smem (fp16, double-buffered). Per nc: 2 K-blocks of 128,
// 4 CTA syncs, all cp.async waits hidden.
// ---------------------------------------------------------------------------
__global__ __launch_bounds__(THREADS_R, 1) void rnn_kernel(
    const float* __restrict__ bih,
    const float* __restrict__ bhh,
    float* __restrict__ fin)
{
    extern __shared__ char smc[];
    const uint32_t sb = smem_u32(smc);
    const int tid = threadIdx.x;
    const int lane = tid & 31, wid = tid >> 5;
    const int warp_m = wid & 3, wn = wid >> 2;
    const int gm = blockIdx.x * RTILE_M;
    const int gmL = gm & (L_DIM - 1);

    const int lr8  = lane & 7;
    const int lbit = (lane >> 3) & 1;
    const int lhi  = lane >> 4;
    const int rl = lane >> 2, cl = (lane & 3) * 2;
    const int colb = wn * 16;

    // W block loader: nc4 = n-chunk (0..3), b = K-block (0..1), buf = ring slot
    auto issueW = [&](int nc4, int b, int buf) {
        const uint32_t bbase = sb + SB_OFF + buf * WBUF;
        const int n0w = nc4 * 64;
#pragma unroll
        for (int i = 0; i < 6; i++) {
            int j = tid + i * THREADS_R;         // 0..3071 chunks of 16B
            int row = j >> 4, q = j & 15;
            int g = row >> 6, nl = row & 63;
            CP_ASYNC16(bbase + row * 256 + ((q * 16) ^ ((row & 7) << 4)),
                       &g_Whh_h[(size_t)(g * H_DIM + n0w + nl) * KDIM + b * 128 + q * 8]);
        }
        CP_COMMIT();
    };

    // ---- t = 0: h0 from G (h starts at zero) -> HH0 (fp16) ----
    for (int j = tid; j < RTILE_M * 128; j += THREADS_R) {
        int r = j >> 7;
        int cp = (j & 127) * 2;
        int grow = gm + r;
        bool valid = (gmL + r - (KWIN - 1)) >= 0;
        float2 gir, giz, gin;
        if (valid) {
            const __half* Gp = &g_Gh[(size_t)(grow - (KWIN - 1)) * G3];
            gir = __half22float2(*(const __half2*)&Gp[cp]);
            giz = __half22float2(*(const __half2*)&Gp[H_DIM + cp]);
            gin = __half22float2(*(const __half2*)&Gp[2 * H_DIM + cp]);
        } else {
            gir = *(const float2*)&bih[cp];
            giz = *(const float2*)&bih[H_DIM + cp];
            gin = *(const float2*)&bih[2 * H_DIM + cp];
        }
        float2 br = *(const float2*)&bhh[cp];
        float2 bz = *(const float2*)&bhh[H_DIM + cp];
        float2 bn = *(const float2*)&bhh[2 * H_DIM + cp];
        float2 o;
        {
            float rr = sigm(gir.x + br.x);
            float zz = sigm(giz.x + bz.x);
            float nn = tanh_apx(gin.x + rr * bn.x);
            o.x = (1.0f - zz) * nn;
        }
        {
            float rr = sigm(gir.y + br.y);
            float zz = sigm(giz.y + bz.y);
            float nn = tanh_apx(gin.y + rr * bn.y);
            o.y = (1.0f - zz) * nn;
        }
        *(__half2*)(smc + HH_OFF + r * 512 + ((cp * 2) ^ ((r & 7) << 4))) =
            __float22half2_rn(o);
    }
    __syncthreads();

    // prime: nc=0's two W blocks
    issueW(0, 0, 0);
    issueW(0, 1, 1);

    // ---- steps t = 1..15 ----
#pragma unroll 1
    for (int t = 1; t < KWIN; t++) {
        const int cur = (t - 1) & 1;
        const int nxt = t & 1;
        const int t0 = t - (KWIN - 1);
        const bool last = (t == KWIN - 1);
        const uint32_t sA = sb + HH_OFF + cur * HH_BUF;

#pragma unroll 1
        for (int nc = 0; nc < 4; nc++) {
            const int n0 = nc * 64;
            const int fb = nc & 1;               // buf holding K-block 0

            float acc[3][2][2][4];
#pragma unroll
            for (int g = 0; g < 3; g++)
#pragma unroll
                for (int mt = 0; mt < 2; mt++)
#pragma unroll
                    for (int nt = 0; nt < 2; nt++)
#pragma unroll
                        for (int e = 0; e < 4; e++) acc[g][mt][nt][e] = 0.0f;

            auto compute_block = [&](int b, int buf) {
                const uint32_t sBb = sb + SB_OFF + buf * WBUF;
#pragma unroll
                for (int ks = 0; ks < 8; ks++) {
                    uint32_t a[2][4];
#pragma unroll
                    for (int mt = 0; mt < 2; mt++) {
                        int row = warp_m * 32 + mt * 16 + lr8 + 8 * lbit;
                        int kbyte = b * 256 + ks * 32 + lhi * 16;
                        LDSM_X4(a[mt][0], a[mt][1], a[mt][2], a[mt][3],
                                sA + row * 512 + (kbyte ^ ((row & 7) << 4)));
                    }
#pragma unroll
                    for (int g = 0; g < 3; g++) {
                        uint32_t b4[4];
                        int row = g * 64 + wn * 16 + lr8 + 8 * lhi;
                        int kbyte = ks * 32 + lbit * 16;
                        LDSM_X4(b4[0], b4[1], b4[2], b4[3],
                                sBb + row * 256 + (kbyte ^ ((row & 7) << 4)));
#pragma unroll
                        for (int mt = 0; mt < 2; mt++) {
                            mma_f16(acc[g][mt][0], a[mt], b4[0], b4[1]);
                            mma_f16(acc[g][mt][1], a[mt], b4[2], b4[3]);
                        }
                    }
                }
            };

            // ---- K-block 0 (buf fb); kb1 already in flight ----
            CP_WAIT(1);                 // pending {kb0, kb1} -> kb0 landed
            __syncthreads();
            compute_block(0, fb);

            // ---- kb1 ready; G(nc) streams into drained fb region ----
            CP_WAIT(0);                 // pending {kb1} -> kb1 landed
            __syncthreads();            // all warps done reading fb
            {                           // fp16 G stage -> fb buffer
                const uint32_t gbase = sb + SB_OFF + fb * WBUF;
#pragma unroll
                for (int i = 0; i < 6; i++) {
                    int j = tid + i * THREADS_R;     // 0..3071
                    int r = j / 24, c = j % 24;
                    int g = c >> 3, q = c & 7;
                    if (gmL + r + t0 >= 0)
                        CP_ASYNC16(gbase + r * 384 + ((c * 16) ^ ((r & 7) << 4)),
                                   &g_Gh[(size_t)(gm + r + t0) * G3 + g * H_DIM + n0 + q * 8]);
                }
                CP_COMMIT();
            }
            compute_block(1, 1 - fb);

            // ---- G ready; prefetch next-nc kb0 under the epilogue ----
            CP_WAIT(0);                 // pending {G} -> G landed
            __syncthreads();            // all warps done reading 1-fb
            issueW((nc + 1) & 3, 0, 1 - fb);

            // GRU epilogue: G from staged smem (fb), h (fp16) from HH cur
#pragma unroll
            for (int mt = 0; mt < 2; mt++)
#pragma unroll
                for (int rp = 0; rp < 2; rp++) {
                    int rloc = warp_m * 32 + mt * 16 + rp * 8 + rl;
                    bool valid = (gmL + rloc + t0) >= 0;
                    int sw = (rloc & 7) << 4;
#pragma unroll
                    for (int nt = 0; nt < 2; nt++) {
                        int cloc = colb + nt * 8 + cl;
                        int col = n0 + cloc;
                        float2 gr, gz, gn;
                        if (valid) {
                            const char* gp = smc + SB_OFF + fb * WBUF + rloc * 384;
#pragma unroll
                            for (int g = 0; g < 3; g++) {
                                int b = (g * 64 + cloc) * 2;
                                float2 v = __half22float2(
                                    *(const __half2*)(gp + ((b & ~15) ^ sw) + (b & 15)));
                                if (g == 0) gr = v; else if (g == 1) gz = v; else gn = v;
                            }
                        } else {
                            gr = *(const float2*)&bih[col];
                            gz = *(const float2*)&bih[H_DIM + col];
                            gn = *(const float2*)&bih[2 * H_DIM + col];
                        }
                        float2 br = *(const float2*)&bhh[col];
                        float2 bz = *(const float2*)&bhh[H_DIM + col];
                        float2 bn = *(const float2*)&bhh[2 * H_DIM + col];
                        float2 h = __half22float2(*(const __half2*)(
                            smc + HH_OFF + cur * HH_BUF + rloc * 512 + ((col * 2) ^ sw)));
                        float2 o;
                        {
                            float r  = sigm(gr.x + acc[0][mt][nt][rp * 2] + br.x);
                            float z  = sigm(gz.x + acc[1][mt][nt][rp * 2] + bz.x);
                            float nn = tanh_apx(gn.x + r * (acc[2][mt][nt][rp * 2] + bn.x));
                            o.x = (1.0f - z) * nn + z * h.x;
                        }
                        {
                            float r  = sigm(gr.y + acc[0][mt][nt][rp * 2 + 1] + br.y);
                            float z  = sigm(gz.y + acc[1][mt][nt][rp * 2 + 1] + bz.y);
                            float nn = tanh_apx(gn.y + r * (acc[2][mt][nt][rp * 2 + 1] + bn.y));
                            o.y = (1.0f - z) * nn + z * h.y;
                        }
                        if (last) {
                            // stage f32 out in the (unused) HH nxt buffer
                            int hb = cloc * 4;
                            *(float2*)(smc + HH_OFF + nxt * HH_BUF + rloc * 256 +
                                       ((hb & ~15) ^ sw) + (hb & 15)) = o;
                        } else {
                            *(__half2*)(smc + HH_OFF + nxt * HH_BUF + rloc * 512 +
                                        ((col * 2) ^ sw)) = __float22half2_rn(o);
                        }
                    }
                }
            __syncthreads();            // epilogue done: fb (G) region free
            issueW((nc + 1) & 3, 1, fb);   // prefetch next-nc kb1

            if (last) {                 // coalesced final store
#pragma unroll
                for (int i = 0; i < 4; i++) {
                    int j = tid + i * THREADS_R;     // 2048 float4
                    int r = j >> 4, q = j & 15;
                    float4 v = *(const float4*)(smc + HH_OFF + nxt * HH_BUF + r * 256 +
                                                ((q * 16) ^ ((r & 7) << 4)));
                    *(float4*)&fin[(size_t)(gm + r) * H_DIM + n0 + q * 4] = v;
                }
                __syncthreads();
            }
        }
    }
}

// ---------------------------------------------------------------------------
// Launch: prep -> proj -> persistent rnn (3 launches total)
// ---------------------------------------------------------------------------
extern "C" void kernel_launch(void* const* d_in, const int* in_sizes, int n_in,
                              void* d_out, int out_size)
{
    const float* x   = (const float*)d_in[0];
    const float* Wih = (const float*)d_in[1];
    const float* Whh = (const float*)d_in[2];
    const float* bih = (const float*)d_in[3];
    const float* bhh = (const float*)d_in[4];
    float* out = (float*)d_out;

    cudaFuncSetAttribute(proj_kernel, cudaFuncAttributeMaxDynamicSharedMemorySize, PROJ_SMEM);
    cudaFuncSetAttribute(rnn_kernel,  cudaFuncAttributeMaxDynamicSharedMemorySize, RNN_SMEM);

    prep_kernel<<<(R_TOTAL * KDIM / 4 + 255) / 256, 256>>>(x, Wih, Whh);
    dim3 pgrid(R_TOTAL / TILE_M, H_DIM / 64);   // (256, 4)
    proj_kernel<<<pgrid, THREADS, PROJ_SMEM>>>(bih);
    rnn_kernel<<<R_TOTAL / RTILE_M, THREADS_R, RNN_SMEM>>>(bih, bhh, out);
}

// round 17
// speedup vs baseline: 2.9749x; 1.0453x over previous
#include <cuda_runtime.h>
#include <cuda_fp16.h>
#include <cstdint>

// Problem dims (fixed)
#define L_DIM   1024
#define H_DIM   256
#define KWIN    16
#define R_TOTAL 16384
#define G3      768
#define KDIM    256

// ---------------- persistent rnn kernel: M=128/CTA, 512 thr, 1 CTA/SM ------
#define THREADS_R 512
#define RTILE_M   128
// HH: fp16 H double buffer, [128 rows][256 halves] per buf, 512B/row, swizzled
#define HH_OFF   0
#define HH_BUF   65536
// W ring: 2 x [192 rows][128 halves] bufs (49152B each, 256B/row, swizzled).
// G stage (fp16, 128 rows x 384B) reuses the kb0 buffer after it drains.
#define SB_OFF   131072
#define WBUF     49152
// Bias park: bih_h [768 halves] + bhh_h [768 halves] = 3072 B
#define BIAS_OFF 229376
#define RNN_SMEM 232448     // 227KB exactly -> 1 CTA/SM

// ---------------- proj kernel (unchanged, M=64, 2 CTAs/SM) ----------------
#define THREADS 256
#define TILE_M  64
#define NTOT    192
#define BK      64
#define NCHUNK  (KDIM / BK)
#define AS      72
#define BS      72
#define ABUF    (TILE_M * AS)
#define BBUF    (NTOT * BS)
#define BUFF    (ABUF + BBUF)
#define PROJ_SMEM (3 * BUFF * 2)    // 110592
#define SG_OFF  0

// Scratch (allocation-free rule: device globals)
__device__ __half g_Gh[R_TOTAL * G3];       // input projections incl. b_ih (fp16)
__device__ __half g_Xh[R_TOTAL * KDIM];     // fp16 x
__device__ __half g_Wih_h[G3 * KDIM];       // fp16 W_ih
__device__ __half g_Whh_h[G3 * KDIM];       // fp16 W_hh

// ---------------------------------------------------------------------------
// helpers
// ---------------------------------------------------------------------------
__device__ __forceinline__ uint32_t smem_u32(const void* p) {
    uint32_t a;
    asm("{ .reg .u64 t; cvta.to.shared.u64 t, %1; cvt.u32.u64 %0, t; }" : "=r"(a) : "l"(p));
    return a;
}
__device__ __forceinline__ float tanh_apx(float x) {
    float y; asm("tanh.approx.f32 %0, %1;" : "=f"(y) : "f"(x)); return y;
}
__device__ __forceinline__ float sigm(float x) {
    return fmaf(tanh_apx(0.5f * x), 0.5f, 0.5f);
}
__device__ __forceinline__ uint32_t h2_bits(__half2 h) {
    uint32_t u; __builtin_memcpy(&u, &h, 4); return u;
}
__device__ __forceinline__ __half2 tanh2(__half2 x) {
    uint32_t xi = h2_bits(x), yi;
    asm("tanh.approx.f16x2 %0, %1;" : "=r"(yi) : "r"(xi));
    __half2 y; __builtin_memcpy(&y, &yi, 4); return y;
}
__device__ __forceinline__ __half2 sigm2(__half2 x) {
    const __half2 h05 = __float2half2_rn(0.5f);
    return __hfma2(tanh2(__hmul2(x, h05)), h05, h05);
}

#define CP_ASYNC16(dst, src) \
    asm volatile("cp.async.cg.shared.global [%0], [%1], 16;" :: "r"(dst), "l"(src) : "memory")
#define CP_COMMIT() asm volatile("cp.async.commit_group;" ::: "memory")
#define CP_WAIT(n)  asm volatile("cp.async.wait_group %0;" :: "n"(n) : "memory")

#define LDSM_X4(r0, r1, r2, r3, addr)                                        \
    asm volatile("ldmatrix.sync.aligned.m8n8.x4.shared.b16 {%0,%1,%2,%3}, [%4];" \
        : "=r"(r0), "=r"(r1), "=r"(r2), "=r"(r3) : "r"(addr))

__device__ __forceinline__ void mma_f16(float* d, const uint32_t* a, uint32_t b0, uint32_t b1) {
    asm volatile(
        "mma.sync.aligned.m16n8k16.row.col.f32.f16.f16.f32 "
        "{%0,%1,%2,%3}, {%4,%5,%6,%7}, {%8,%9}, {%0,%1,%2,%3};"
        : "+f"(d[0]), "+f"(d[1]), "+f"(d[2]), "+f"(d[3])
        : "r"(a[0]), "r"(a[1]), "r"(a[2]), "r"(a[3]), "r"(b0), "r"(b1));
}

// ---------------------------------------------------------------------------
// prep: convert x, W_ih, W_hh to fp16 (RN), float4-vectorized
// ---------------------------------------------------------------------------
__global__ __launch_bounds__(256) void prep_kernel(
    const float* __restrict__ x,
    const float* __restrict__ Wih,
    const float* __restrict__ Whh)
{
    int i = (blockIdx.x * 256 + threadIdx.x) * 4;
    if (i < R_TOTAL * KDIM) {
        float4 v = *(const float4*)&x[i];
        uint2 o;
        o.x = h2_bits(__floats2half2_rn(v.x, v.y));
        o.y = h2_bits(__floats2half2_rn(v.z, v.w));
        *(uint2*)&g_Xh[i] = o;
    }
    if (i < G3 * KDIM) {
        float4 v = *(const float4*)&Wih[i];
        uint2 o;
        o.x = h2_bits(__floats2half2_rn(v.x, v.y));
        o.y = h2_bits(__floats2half2_rn(v.z, v.w));
        *(uint2*)&g_Wih_h[i] = o;
        float4 w = *(const float4*)&Whh[i];
        o.x = h2_bits(__floats2half2_rn(w.x, w.y));
        o.y = h2_bits(__floats2half2_rn(w.z, w.w));
        *(uint2*)&g_Whh_h[i] = o;
    }
}

// ---------------------------------------------------------------------------
// proj kernel: G = x @ W_ih^T + b_ih  -> g_Gh (fp16), staged coalesced store
// ---------------------------------------------------------------------------
__global__ __launch_bounds__(THREADS, 2) void proj_kernel(const float* __restrict__ bih)
{
    extern __shared__ __half smf[];
    char* const smc = (char*)smf;
    const uint32_t sb = smem_u32(smf);
    const int tid = threadIdx.x;
    const int lane = tid & 31, wid = tid >> 5;
    const int warp_m = wid & 1, wn = wid >> 1;
    const int gm = blockIdx.x * TILE_M;
    const int n0 = blockIdx.y * 64;

    float acc[3][2][2][4];
#pragma unroll
    for (int g = 0; g < 3; g++)
#pragma unroll
        for (int mt = 0; mt < 2; mt++)
#pragma unroll
            for (int nt = 0; nt < 2; nt++)
#pragma unroll
                for (int e = 0; e < 4; e++) acc[g][mt][nt][e] = 0.0f;

    auto issue = [&](int k0, int buf) {
        const uint32_t abase = sb + buf * (BUFF * 2);
#pragma unroll
        for (int i = 0; i < 2; i++) {
            int j = tid + i * THREADS;
            int row = j >> 3, kv = (j & 7) << 3;
            CP_ASYNC16(abase + (row * AS + kv) * 2,
                       &g_Xh[(size_t)(gm + row) * KDIM + k0 + kv]);
        }
        const uint32_t bbase = abase + ABUF * 2;
#pragma unroll
        for (int i = 0; i < 6; i++) {
            int j = tid + i * THREADS;
            int row = j >> 3, kv = (j & 7) << 3;
            int g = row >> 6, nl = row & 63;
            CP_ASYNC16(bbase + (row * BS + kv) * 2,
                       &g_Wih_h[(size_t)(g * H_DIM + n0 + nl) * KDIM + k0 + kv]);
        }
        CP_COMMIT();
    };

    const int lr8  = lane & 7;
    const int lbit = (lane >> 3) & 1;
    const int lhi  = lane >> 4;

    issue(0, 0);
    issue(BK, 1);
#pragma unroll 1
    for (int c = 0; c < NCHUNK; c++) {
        if (c == NCHUNK - 1) { CP_WAIT(0); } else { CP_WAIT(1); }
        __syncthreads();
        if (c + 2 < NCHUNK) issue((c + 2) * BK, (c + 2) % 3);

        const uint32_t sA = sb + (c % 3) * (BUFF * 2);
        const uint32_t sB = sA + ABUF * 2;
#pragma unroll
        for (int ks = 0; ks < 4; ks++) {
            const int kk = ks * 16;
            uint32_t a[2][4];
#pragma unroll
            for (int mt = 0; mt < 2; mt++) {
                int row = warp_m * 32 + mt * 16 + lr8 + 8 * lbit;
                int col = kk + 8 * lhi;
                LDSM_X4(a[mt][0], a[mt][1], a[mt][2], a[mt][3],
                        sA + (row * AS + col) * 2);
            }
#pragma unroll
            for (int g = 0; g < 3; g++) {
                uint32_t b[4];
                int row = g * 64 + wn * 16 + lr8 + 8 * lhi;
                int col = kk + 8 * lbit;
                LDSM_X4(b[0], b[1], b[2], b[3], sB + (row * BS + col) * 2);
#pragma unroll
                for (int mt = 0; mt < 2; mt++) {
                    mma_f16(acc[g][mt][0], a[mt], b[0], b[1]);
                    mma_f16(acc[g][mt][1], a[mt], b[2], b[3]);
                }
            }
        }
    }
    __syncthreads();

    const int rl = lane >> 2, cl = (lane & 3) * 2;
    const int colb = wn * 16;
#pragma unroll
    for (int mt = 0; mt < 2; mt++)
#pragma unroll
        for (int rp = 0; rp < 2; rp++) {
            int rloc = warp_m * 32 + mt * 16 + rp * 8 + rl;
            int sw = (rloc & 7) << 4;
#pragma unroll
            for (int g = 0; g < 3; g++)
#pragma unroll
                for (int nt = 0; nt < 2; nt++) {
                    int cloc = colb + nt * 8 + cl;
                    float2 bv = *(const float2*)&bih[g * H_DIM + n0 + cloc];
                    int b = (g * 64 + cloc) * 2;
                    *(__half2*)(smc + SG_OFF + rloc * 384 + ((b & ~15) ^ sw) + (b & 15)) =
                        __floats2half2_rn(acc[g][mt][nt][rp * 2 + 0] + bv.x,
                                          acc[g][mt][nt][rp * 2 + 1] + bv.y);
                }
        }
    __syncthreads();
    for (int j = tid; j < 64 * 24; j += THREADS) {
        int r = j / 24, c = j % 24;
        int g = c >> 3, q = c & 7;
        uint4 v = *(const uint4*)(smc + SG_OFF + r * 384 + ((c * 16) ^ ((r & 7) << 4)));
        *(uint4*)&g_Gh[(size_t)(gm + r) * G3 + g * H_DIM + n0 + q * 8] = v;
    }
}

// ---------------------------------------------------------------------------
// Persistent RNN kernel: one CTA owns 128 rows x ALL 768 gate cols; h state
// lives ONLY in smem (fp16, double-buffered). Half2 epilogue, biases in smem.
// ---------------------------------------------------------------------------
__global__ __launch_bounds__(THREADS_R, 1) void rnn_kernel(
    const float* __restrict__ bih,
    const float* __restrict__ bhh,
    float* __restrict__ fin)
{
    extern __shared__ char smc[];
    const uint32_t sb = smem_u32(smc);
    const int tid = threadIdx.x;
    const int lane = tid & 31, wid = tid >> 5;
    const int warp_m = wid & 3, wn = wid >> 2;
    const int gm = blockIdx.x * RTILE_M;
    const int gmL = gm & (L_DIM - 1);

    const int lr8  = lane & 7;
    const int lbit = (lane >> 3) & 1;
    const int lhi  = lane >> 4;
    const int rl = lane >> 2, cl = (lane & 3) * 2;
    const int colb = wn * 16;

    // W block loader: nc4 = n-chunk (0..3), b = K-block (0..1), buf = ring slot
    auto issueW = [&](int nc4, int b, int buf) {
        const uint32_t bbase = sb + SB_OFF + buf * WBUF;
        const int n0w = nc4 * 64;
#pragma unroll
        for (int i = 0; i < 6; i++) {
            int j = tid + i * THREADS_R;         // 0..3071 chunks of 16B
            int row = j >> 4, q = j & 15;
            int g = row >> 6, nl = row & 63;
            CP_ASYNC16(bbase + row * 256 + ((q * 16) ^ ((row & 7) << 4)),
                       &g_Whh_h[(size_t)(g * H_DIM + n0w + nl) * KDIM + b * 128 + q * 8]);
        }
        CP_COMMIT();
    };

    // ---- bias park (fp16) ----
    for (int j = tid; j < G3; j += THREADS_R) {
        *(__half*)(smc + BIAS_OFF + j * 2)        = __float2half(bih[j]);
        *(__half*)(smc + BIAS_OFF + 1536 + j * 2) = __float2half(bhh[j]);
    }

    // ---- t = 0: h0 from G (h starts at zero) -> HH0 (fp16) ----
    for (int j = tid; j < RTILE_M * 128; j += THREADS_R) {
        int r = j >> 7;
        int cp = (j & 127) * 2;
        int grow = gm + r;
        bool valid = (gmL + r - (KWIN - 1)) >= 0;
        float2 gir, giz, gin;
        if (valid) {
            const __half* Gp = &g_Gh[(size_t)(grow - (KWIN - 1)) * G3];
            gir = __half22float2(*(const __half2*)&Gp[cp]);
            giz = __half22float2(*(const __half2*)&Gp[H_DIM + cp]);
            gin = __half22float2(*(const __half2*)&Gp[2 * H_DIM + cp]);
        } else {
            gir = *(const float2*)&bih[cp];
            giz = *(const float2*)&bih[H_DIM + cp];
            gin = *(const float2*)&bih[2 * H_DIM + cp];
        }
        float2 br = *(const float2*)&bhh[cp];
        float2 bz = *(const float2*)&bhh[H_DIM + cp];
        float2 bn = *(const float2*)&bhh[2 * H_DIM + cp];
        float2 o;
        {
            float rr = sigm(gir.x + br.x);
            float zz = sigm(giz.x + bz.x);
            float nn = tanh_apx(gin.x + rr * bn.x);
            o.x = (1.0f - zz) * nn;
        }
        {
            float rr = sigm(gir.y + br.y);
            float zz = sigm(giz.y + bz.y);
            float nn = tanh_apx(gin.y + rr * bn.y);
            o.y = (1.0f - zz) * nn;
        }
        *(__half2*)(smc + HH_OFF + r * 512 + ((cp * 2) ^ ((r & 7) << 4))) =
            __float22half2_rn(o);
    }
    __syncthreads();

    // prime: nc=0's two W blocks
    issueW(0, 0, 0);
    issueW(0, 1, 1);

    // ---- steps t = 1..15 ----
#pragma unroll 1
    for (int t = 1; t < KWIN; t++) {
        const int cur = (t - 1) & 1;
        const int nxt = t & 1;
        const int t0 = t - (KWIN - 1);
        const bool last = (t == KWIN - 1);
        const uint32_t sA = sb + HH_OFF + cur * HH_BUF;

#pragma unroll 1
        for (int nc = 0; nc < 4; nc++) {
            const int n0 = nc * 64;
            const int fb = nc & 1;               // buf holding K-block 0

            float acc[3][2][2][4];
#pragma unroll
            for (int g = 0; g < 3; g++)
#pragma unroll
                for (int mt = 0; mt < 2; mt++)
#pragma unroll
                    for (int nt = 0; nt < 2; nt++)
#pragma unroll
                        for (int e = 0; e < 4; e++) acc[g][mt][nt][e] = 0.0f;

            auto compute_block = [&](int b, int buf) {
                const uint32_t sBb = sb + SB_OFF + buf * WBUF;
#pragma unroll
                for (int ks = 0; ks < 8; ks++) {
                    uint32_t a[2][4];
#pragma unroll
                    for (int mt = 0; mt < 2; mt++) {
                        int row = warp_m * 32 + mt * 16 + lr8 + 8 * lbit;
                        int kbyte = b * 256 + ks * 32 + lhi * 16;
                        LDSM_X4(a[mt][0], a[mt][1], a[mt][2], a[mt][3],
                                sA + row * 512 + (kbyte ^ ((row & 7) << 4)));
                    }
#pragma unroll
                    for (int g = 0; g < 3; g++) {
                        uint32_t b4[4];
                        int row = g * 64 + wn * 16 + lr8 + 8 * lhi;
                        int kbyte = ks * 32 + lbit * 16;
                        LDSM_X4(b4[0], b4[1], b4[2], b4[3],
                                sBb + row * 256 + (kbyte ^ ((row & 7) << 4)));
#pragma unroll
                        for (int mt = 0; mt < 2; mt++) {
                            mma_f16(acc[g][mt][0], a[mt], b4[0], b4[1]);
                            mma_f16(acc[g][mt][1], a[mt], b4[2], b4[3]);
                        }
                    }
                }
            };

            // ---- K-block 0 (buf fb); kb1 already in flight ----
            CP_WAIT(1);                 // pending {kb0, kb1} -> kb0 landed
            __syncthreads();
            compute_block(0, fb);

            // ---- kb1 ready; G(nc) streams into drained fb region ----
            CP_WAIT(0);                 // pending {kb1} -> kb1 landed
            __syncthreads();            // all warps done reading fb
            {                           // fp16 G stage -> fb buffer
                const uint32_t gbase = sb + SB_OFF + fb * WBUF;
#pragma unroll
                for (int i = 0; i < 6; i++) {
                    int j = tid + i * THREADS_R;     // 0..3071
                    int r = j / 24, c = j % 24;
                    int g = c >> 3, q = c & 7;
                    if (gmL + r + t0 >= 0)
                        CP_ASYNC16(gbase + r * 384 + ((c * 16) ^ ((r & 7) << 4)),
                                   &g_Gh[(size_t)(gm + r + t0) * G3 + g * H_DIM + n0 + q * 8]);
                }
                CP_COMMIT();
            }
            compute_block(1, 1 - fb);

            // ---- G ready; prefetch next-nc kb0 under the epilogue ----
            CP_WAIT(0);                 // pending {G} -> G landed
            __syncthreads();            // all warps done reading 1-fb
            issueW((nc + 1) & 3, 0, 1 - fb);

            // half2 GRU epilogue: G staged (fb), h from HH cur, biases in smem
#pragma unroll
            for (int mt = 0; mt < 2; mt++)
#pragma unroll
                for (int rp = 0; rp < 2; rp++) {
                    int rloc = warp_m * 32 + mt * 16 + rp * 8 + rl;
                    bool valid = (gmL + rloc + t0) >= 0;
                    int sw = (rloc & 7) << 4;
#pragma unroll
                    for (int nt = 0; nt < 2; nt++) {
                        int cloc = colb + nt * 8 + cl;
                        int col = n0 + cloc;
                        __half2 gr, gz, gn;
                        if (valid) {
                            const char* gp = smc + SB_OFF + fb * WBUF + rloc * 384;
#pragma unroll
                            for (int g = 0; g < 3; g++) {
                                int b = (g * 64 + cloc) * 2;
                                __half2 v = *(const __half2*)(gp + ((b & ~15) ^ sw) + (b & 15));
                                if (g == 0) gr = v; else if (g == 1) gz = v; else gn = v;
                            }
                        } else {
                            gr = *(const __half2*)(smc + BIAS_OFF + col * 2);
                            gz = *(const __half2*)(smc + BIAS_OFF + (H_DIM + col) * 2);
                            gn = *(const __half2*)(smc + BIAS_OFF + (2 * H_DIM + col) * 2);
                        }
                        __half2 br = *(const __half2*)(smc + BIAS_OFF + 1536 + col * 2);
                        __half2 bz = *(const __half2*)(smc + BIAS_OFF + 1536 + (H_DIM + col) * 2);
                        __half2 bn = *(const __half2*)(smc + BIAS_OFF + 1536 + (2 * H_DIM + col) * 2);
                        __half2 h = *(const __half2*)(
                            smc + HH_OFF + cur * HH_BUF + rloc * 512 + ((col * 2) ^ sw));
                        __half2 ghr = __floats2half2_rn(acc[0][mt][nt][rp * 2], acc[0][mt][nt][rp * 2 + 1]);
                        __half2 ghz = __floats2half2_rn(acc[1][mt][nt][rp * 2], acc[1][mt][nt][rp * 2 + 1]);
                        __half2 ghn = __floats2half2_rn(acc[2][mt][nt][rp * 2], acc[2][mt][nt][rp * 2 + 1]);
                        __half2 r2 = sigm2(__hadd2(__hadd2(gr, ghr), br));
                        __half2 z2 = sigm2(__hadd2(__hadd2(gz, ghz), bz));
                        __half2 n2 = tanh2(__hfma2(r2, __hadd2(ghn, bn), gn));
                        __half2 o2 = __hfma2(z2, __hsub2(h, n2), n2);  // n + z*(h-n)
                        if (last) {
                            float2 of = __half22float2(o2);
                            int hb = cloc * 4;
                            *(float2*)(smc + HH_OFF + nxt * HH_BUF + rloc * 256 +
                                       ((hb & ~15) ^ sw) + (hb & 15)) = of;
                        } else {
                            *(__half2*)(smc + HH_OFF + nxt * HH_BUF + rloc * 512 +
                                        ((col * 2) ^ sw)) = o2;
                        }
                    }
                }
            __syncthreads();            // epilogue done: fb (G) region free
            issueW((nc + 1) & 3, 1, fb);   // prefetch next-nc kb1

            if (last) {                 // coalesced final store
#pragma unroll
                for (int i = 0; i < 4; i++) {
                    int j = tid + i * THREADS_R;     // 2048 float4
                    int r = j >> 4, q = j & 15;
                    float4 v = *(const float4*)(smc + HH_OFF + nxt * HH_BUF + r * 256 +
                                                ((q * 16) ^ ((r & 7) << 4)));
                    *(float4*)&fin[(size_t)(gm + r) * H_DIM + n0 + q * 4] = v;
                }
                __syncthreads();
            }
        }
    }
}

// ---------------------------------------------------------------------------
// Launch: prep -> proj -> persistent rnn (3 launches total)
// ---------------------------------------------------------------------------
extern "C" void kernel_launch(void* const* d_in, const int* in_sizes, int n_in,
                              void* d_out, int out_size)
{
    const float* x   = (const float*)d_in[0];
    const float* Wih = (const float*)d_in[1];
    const float* Whh = (const float*)d_in[2];
    const float* bih = (const float*)d_in[3];
    const float* bhh = (const float*)d_in[4];
    float* out = (float*)d_out;

    cudaFuncSetAttribute(proj_kernel, cudaFuncAttributeMaxDynamicSharedMemorySize, PROJ_SMEM);
    cudaFuncSetAttribute(rnn_kernel,  cudaFuncAttributeMaxDynamicSharedMemorySize, RNN_SMEM);

    prep_kernel<<<(R_TOTAL * KDIM / 4 + 255) / 256, 256>>>(x, Wih, Whh);
    dim3 pgrid(R_TOTAL / TILE_M, H_DIM / 64);   // (256, 4)
    proj_kernel<<<pgrid, THREADS, PROJ_SMEM>>>(bih);
    rnn_kernel<<<R_TOTAL / RTILE_M, THREADS_R, RNN_SMEM>>>(bih, bhh, out);
}